// round 13
// baseline (speedup 1.0000x reference)
#include <cuda_runtime.h>
#include <cuda_bf16.h>
#include <cstdint>

#define BATCH 64
#define LSEQ  500
#define FEAT  256
#define HEADS 4
#define DK    64
#define BH    (BATCH*HEADS)       // 256
#define MROWS (BATCH*LSEQ)        // 32000
#define LPAD  512
#define AST   72                  // smem row stride (bf16 elems) -> 144B

// ---------------- device scratch ----------------
static __device__ __nv_bfloat16 g_wqsT_hi[FEAT*FEAT], g_wqsT_lo[FEAT*FEAT];
static __device__ __nv_bfloat16 g_wvsT_hi[FEAT*FEAT], g_wvsT_lo[FEAT*FEAT];
static __device__ __nv_bfloat16 g_fcwT_hi[FEAT*FEAT], g_fcwT_lo[FEAT*FEAT];
static __device__ __nv_bfloat16 g_w1t_hi[DK*DK],      g_w1t_lo[DK*DK];
static __device__ __nv_bfloat16 g_w2t_hi[LPAD*DK],    g_w2t_lo[LPAD*DK];
static __device__ float         g_b2p[LPAD];
static __device__ __nv_bfloat16 g_qh_hi[BH*LSEQ*DK + 1024], g_qh_lo[BH*LSEQ*DK + 1024];
static __device__ __nv_bfloat16 g_vh_hi[BH*LSEQ*DK + 1024], g_vh_lo[BH*LSEQ*DK + 1024]; // [bh][l][d]
static __device__ __nv_bfloat16 g_pre_hi[MROWS*FEAT], g_pre_lo[MROWS*FEAT];

// ---------------- helpers ----------------
__device__ __forceinline__ uint32_t smem_u32(const void* p) {
    uint32_t a;
    asm("{ .reg .u64 t; cvta.to.shared.u64 t, %1; cvt.u32.u64 %0, t; }" : "=r"(a) : "l"(p));
    return a;
}
__device__ __forceinline__ uint32_t pack2(__nv_bfloat16 a, __nv_bfloat16 b) {
    return (uint32_t)__bfloat16_as_ushort(a) | ((uint32_t)__bfloat16_as_ushort(b) << 16);
}
__device__ __forceinline__ void split1(float x, __nv_bfloat16& h, __nv_bfloat16& l) {
    h = __float2bfloat16(x);
    l = __float2bfloat16(x - __bfloat162float(h));
}
__device__ __forceinline__ void split2(float x0, float x1, uint32_t& hi, uint32_t& lo) {
    __nv_bfloat16 h0, l0, h1, l1;
    split1(x0, h0, l0);
    split1(x1, h1, l1);
    hi = pack2(h0, h1);
    lo = pack2(l0, l1);
}

__device__ __forceinline__ void mma_bf16(float acc[4], uint32_t a0, uint32_t a1,
                                         uint32_t a2, uint32_t a3,
                                         uint32_t b0, uint32_t b1) {
    asm volatile(
        "mma.sync.aligned.m16n8k16.row.col.f32.bf16.bf16.f32 "
        "{%0,%1,%2,%3}, {%4,%5,%6,%7}, {%8,%9}, {%0,%1,%2,%3};"
        : "+f"(acc[0]), "+f"(acc[1]), "+f"(acc[2]), "+f"(acc[3])
        : "r"(a0), "r"(a1), "r"(a2), "r"(a3), "r"(b0), "r"(b1));
}
__device__ __forceinline__ void ldsm4(uint32_t& r0, uint32_t& r1, uint32_t& r2, uint32_t& r3,
                                      uint32_t addr) {
    asm volatile("ldmatrix.sync.aligned.m8n8.x4.shared.b16 {%0,%1,%2,%3}, [%4];"
                 : "=r"(r0), "=r"(r1), "=r"(r2), "=r"(r3) : "r"(addr));
}
__device__ __forceinline__ void ldsm4_t(uint32_t& r0, uint32_t& r1, uint32_t& r2, uint32_t& r3,
                                        uint32_t addr) {
    asm volatile("ldmatrix.sync.aligned.m8n8.x4.trans.shared.b16 {%0,%1,%2,%3}, [%4];"
                 : "=r"(r0), "=r"(r1), "=r"(r2), "=r"(r3) : "r"(addr));
}

// LDSM-based 64-deep K chunk: A [>=mw+16][64], B [NF*8][64], stride AST, hi/lo split.
template <int NF>
__device__ __forceinline__ void mma_chunk(float (*acc)[4],
                                          uint32_t aH, uint32_t aL,
                                          uint32_t bH, uint32_t bL,
                                          int mw, int lane) {
    const int r  = lane & 7;
    const int q3 = (lane >> 3) & 1;
    const int q4 = (lane >> 4) & 1;
    const unsigned aoff = (unsigned)(((mw + q3 * 8 + r) * AST + q4 * 8) * 2);
    const unsigned boff = (unsigned)(((q4 * 8 + r) * AST + q3 * 8) * 2);
#pragma unroll
    for (int ks = 0; ks < 4; ks++) {
        uint32_t ah0, ah1, ah2, ah3, al0, al1, al2, al3;
        ldsm4(ah0, ah1, ah2, ah3, aH + aoff + ks * 32);
        ldsm4(al0, al1, al2, al3, aL + aoff + ks * 32);
#pragma unroll
        for (int jp = 0; jp < NF / 2; jp++) {
            uint32_t bh0, bh1, bh2, bh3, bl0, bl1, bl2, bl3;
            unsigned bo = boff + (unsigned)(jp * 16 * AST * 2) + ks * 32;
            ldsm4(bh0, bh1, bh2, bh3, bH + bo);
            ldsm4(bl0, bl1, bl2, bl3, bL + bo);
            mma_bf16(acc[2 * jp],     ah0, ah1, ah2, ah3, bh0, bh1);
            mma_bf16(acc[2 * jp],     ah0, ah1, ah2, ah3, bl0, bl1);
            mma_bf16(acc[2 * jp],     al0, al1, al2, al3, bh0, bh1);
            mma_bf16(acc[2 * jp + 1], ah0, ah1, ah2, ah3, bh2, bh3);
            mma_bf16(acc[2 * jp + 1], ah0, ah1, ah2, ah3, bl2, bl3);
            mma_bf16(acc[2 * jp + 1], al0, al1, al2, al3, bh2, bh3);
        }
    }
}

__device__ __forceinline__ void cp_tile(char* dst, const char* src, int rows,
                                        int valid, int gstride, int tid, int nt) {
    for (int i = tid; i < rows * 8; i += nt) {
        int r = i >> 3, c = (i & 7) << 4;
        uint4 v = make_uint4(0u, 0u, 0u, 0u);
        if (r < valid) v = *(const uint4*)(src + (size_t)r * gstride + c);
        *(uint4*)(dst + r * (AST * 2) + c) = v;
    }
}

__device__ __forceinline__ void cpa16(uint32_t dst, const void* src) {
    asm volatile("cp.async.ca.shared.global [%0], [%1], 16;" :: "r"(dst), "l"(src));
}
#define CP_COMMIT() asm volatile("cp.async.commit_group;" ::: "memory")
#define CP_WAIT(n)  asm volatile("cp.async.wait_group %0;" :: "n"(n) : "memory")

__device__ __forceinline__ void cp_tile_async(uint32_t dst, const char* src,
                                              int rows8, int gstride, int tid, int nt) {
    for (int i = tid; i < rows8; i += nt) {
        int r = i >> 3, c = (i & 7) << 4;
        cpa16(dst + (unsigned)(r * (AST * 2) + c), src + (size_t)r * gstride + c);
    }
}

// ---------------------------------------------------------------------------
__global__ __launch_bounds__(256) void setup_w(const float* __restrict__ w_qs,
                                               const float* __restrict__ w_vs,
                                               const float* __restrict__ fcw,
                                               const float* __restrict__ w1,
                                               const float* __restrict__ w2,
                                               const float* __restrict__ b2) {
    int i0 = blockIdx.x * blockDim.x + threadIdx.x;
    int nt = gridDim.x * blockDim.x;
    for (int t = i0; t < FEAT * FEAT; t += nt) {
        int n = t >> 8, k = t & 255;
        split1(w_qs[k * FEAT + n], g_wqsT_hi[t], g_wqsT_lo[t]);
        split1(w_vs[k * FEAT + n], g_wvsT_hi[t], g_wvsT_lo[t]);
        split1(fcw [k * FEAT + n], g_fcwT_hi[t], g_fcwT_lo[t]);
    }
    for (int t = i0; t < DK * DK; t += nt) {
        int n = t >> 6, k = t & 63;
        split1(w1[k * DK + n], g_w1t_hi[t], g_w1t_lo[t]);
    }
    for (int t = i0; t < LPAD * DK; t += nt) {
        int n = t >> 6, k = t & 63;
        float f = (n < LSEQ) ? w2[k * LSEQ + n] : 0.f;
        split1(f, g_w2t_hi[t], g_w2t_lo[t]);
    }
    for (int t = i0; t < LPAD; t += nt)
        g_b2p[t] = (t < LSEQ) ? b2[t] : -1e30f;
}

// ---------------------------------------------------------------------------
// proj: merged heads. CTA = 64 rows x 256 cols (all 4 heads).
// grid (BATCH*8, 2), block 256, 2 CTAs/SM.
// ---------------------------------------------------------------------------
#define PR_A_HI 0
#define PR_A_LO 9216
#define PR_B_HI 18432
#define PR_B_LO 55296
#define PROJ_SMEM 92160

__global__ __launch_bounds__(256, 2) void proj_kernel(const float* __restrict__ q,
                                                      const float* __restrict__ v) {
    extern __shared__ char sm[];
    const uint32_t sb = smem_u32(sm);
    char* sA_hi = sm + PR_A_HI;
    char* sA_lo = sm + PR_A_LO;

    const int tid = threadIdx.x;
    const int w = tid >> 5, lane = tid & 31, g = lane >> 2, tg = lane & 3;
    const int b = blockIdx.x >> 3, t = blockIdx.x & 7;
    const int which = blockIdx.y;
    const int l0 = t * 64;
    const int nrows = min(64, LSEQ - l0);
    const int m0 = b * LSEQ + l0;
    const int rg = w >> 1;
    const int nh = w & 1;
    const int mw = rg * 16;

    const float* X = which ? v : q;
    const __nv_bfloat16* Wh = which ? g_wvsT_hi : g_wqsT_hi;
    const __nv_bfloat16* Wl = which ? g_wvsT_lo : g_wqsT_lo;
    __nv_bfloat16* Oh = which ? g_vh_hi : g_qh_hi;
    __nv_bfloat16* Ol = which ? g_vh_lo : g_qh_lo;

    float acc[16][4];
#pragma unroll
    for (int j = 0; j < 16; j++)
#pragma unroll
        for (int i = 0; i < 4; i++) acc[j][i] = 0.f;

    const uint32_t bh_base = sb + PR_B_HI + nh * 128 * (AST * 2);
    const uint32_t bl_base = sb + PR_B_LO + nh * 128 * (AST * 2);

    for (int kc = 0; kc < 4; kc++) {
        int k0 = kc * 64;
        __syncthreads();
        for (int i = tid; i < 64 * 16; i += 256) {
            int r = i >> 4, c4 = (i & 15) << 2;
            float4 a = make_float4(0.f, 0.f, 0.f, 0.f);
            if (r < nrows) a = *(const float4*)(X + (size_t)(m0 + r) * FEAT + k0 + c4);
            uint32_t h0, L0, h1, L1;
            split2(a.x, a.y, h0, L0);
            split2(a.z, a.w, h1, L1);
            unsigned off = (unsigned)(r * (AST * 2) + c4 * 2);
            *(uint2*)(sA_hi + off) = make_uint2(h0, h1);
            *(uint2*)(sA_lo + off) = make_uint2(L0, L1);
        }
        cp_tile(sm + PR_B_HI, (const char*)(Wh + k0), 256, 256, FEAT * 2, tid, 256);
        cp_tile(sm + PR_B_LO, (const char*)(Wl + k0), 256, 256, FEAT * 2, tid, 256);
        __syncthreads();
        mma_chunk<16>(acc, sb + PR_A_HI, sb + PR_A_LO, bh_base, bl_base, mw, lane);
    }

#pragma unroll
    for (int rr = 0; rr < 2; rr++) {
        int ml = mw + g + rr * 8;
        if (ml >= nrows) continue;
        int l = l0 + ml;
#pragma unroll
        for (int j = 0; j < 16; j++) {
            int head = nh * 2 + (j >> 3);
            int d = (j & 7) * 8 + tg * 2;
            size_t base = ((size_t)(b * HEADS + head) * LSEQ + l) * DK + d;
            uint32_t hi, lo;
            split2(acc[j][rr * 2], acc[j][rr * 2 + 1], hi, lo);
            *(uint32_t*)(Oh + base) = hi;
            *(uint32_t*)(Ol + base) = lo;
        }
    }
}

// ---------------------------------------------------------------------------
// synth: M-tile 64, 128 threads, no Q smem, depth-2 {W,V} ring -> 3 CTAs/SM.
// ---------------------------------------------------------------------------
#define SY_W   0
#define SY_V   36864
#define SY_B1  73728
#define SYN_SMEM (73728 + 256)

__global__ __launch_bounds__(128, 3) void synth_kernel(const float* __restrict__ b1) {
    extern __shared__ char sm[];
    const uint32_t sb = smem_u32(sm);
    float* b1s = (float*)(sm + SY_B1);

    const int tid = threadIdx.x;
    const int w = tid >> 5, lane = tid & 31, g = lane >> 2, tg = lane & 3;
    const int bh = blockIdx.y;
    const int r0 = blockIdx.x * 64;
    const int nrows = min(64, LSEQ - r0);
    const int mw = w * 16;

    const int r7 = lane & 7;
    const int q3 = (lane >> 3) & 1;
    const int q4 = (lane >> 4) & 1;
    const unsigned bo_n = (unsigned)(((q4 * 8 + r7) * AST + q3 * 8) * 2);
    const unsigned bo_t = (unsigned)(((q3 * 8 + r7) * AST + q4 * 8) * 2);

    const size_t vh_base = (size_t)bh * LSEQ * DK;
    const uint32_t w1b = sb + SY_V + 18432;

    cp_tile_async(w1b,        (const char*)g_w1t_hi, 512, DK * 2, tid, 128);
    cp_tile_async(w1b + 9216, (const char*)g_w1t_lo, 512, DK * 2, tid, 128);
    CP_COMMIT();
    cp_tile_async(sb + SY_W,        (const char*)g_w2t_hi, 512, DK * 2, tid, 128);
    cp_tile_async(sb + SY_W + 9216, (const char*)g_w2t_lo, 512, DK * 2, tid, 128);
    cp_tile_async(sb + SY_V,        (const char*)(g_vh_hi + vh_base), 512, DK * 2, tid, 128);
    cp_tile_async(sb + SY_V + 9216, (const char*)(g_vh_lo + vh_base), 512, DK * 2, tid, 128);
    CP_COMMIT();
    if (tid < 64) b1s[tid] = b1[tid];

    uint32_t qfh[4][4], qfl[4][4];
    {
        const size_t row0 = (size_t)bh * LSEQ + r0 + mw + g;
        const __nv_bfloat16* p0h = g_qh_hi + row0 * DK;
        const __nv_bfloat16* p1h = p0h + 8 * DK;
        const __nv_bfloat16* p0l = g_qh_lo + row0 * DK;
        const __nv_bfloat16* p1l = p0l + 8 * DK;
#pragma unroll
        for (int ks = 0; ks < 4; ks++) {
            int col = ks * 16 + tg * 2;
            qfh[ks][0] = *(const uint32_t*)(p0h + col);
            qfh[ks][1] = *(const uint32_t*)(p1h + col);
            qfh[ks][2] = *(const uint32_t*)(p0h + col + 8);
            qfh[ks][3] = *(const uint32_t*)(p1h + col + 8);
            qfl[ks][0] = *(const uint32_t*)(p0l + col);
            qfl[ks][1] = *(const uint32_t*)(p1l + col);
            qfl[ks][2] = *(const uint32_t*)(p0l + col + 8);
            qfl[ks][3] = *(const uint32_t*)(p1l + col + 8);
        }
    }

    CP_WAIT(1);
    __syncthreads();

    uint32_t hfh[4][4], hfl[4][4];
    {
        float accl[8][4];
#pragma unroll
        for (int j = 0; j < 8; j++)
#pragma unroll
            for (int i = 0; i < 4; i++) accl[j][i] = 0.f;
#pragma unroll
        for (int ks = 0; ks < 4; ks++) {
#pragma unroll
            for (int jp = 0; jp < 4; jp++) {
                uint32_t bh0, bh1, bh2, bh3, bl0, bl1, bl2, bl3;
                unsigned bo = bo_n + (unsigned)(jp * 16 * AST * 2) + ks * 32;
                ldsm4(bh0, bh1, bh2, bh3, w1b + bo);
                ldsm4(bl0, bl1, bl2, bl3, w1b + 9216 + bo);
                mma_bf16(accl[2 * jp],     qfh[ks][0], qfh[ks][1], qfh[ks][2], qfh[ks][3], bh0, bh1);
                mma_bf16(accl[2 * jp],     qfh[ks][0], qfh[ks][1], qfh[ks][2], qfh[ks][3], bl0, bl1);
                mma_bf16(accl[2 * jp],     qfl[ks][0], qfl[ks][1], qfl[ks][2], qfl[ks][3], bh0, bh1);
                mma_bf16(accl[2 * jp + 1], qfh[ks][0], qfh[ks][1], qfh[ks][2], qfh[ks][3], bh2, bh3);
                mma_bf16(accl[2 * jp + 1], qfh[ks][0], qfh[ks][1], qfh[ks][2], qfh[ks][3], bl2, bl3);
                mma_bf16(accl[2 * jp + 1], qfl[ks][0], qfl[ks][1], qfl[ks][2], qfl[ks][3], bh2, bh3);
            }
        }
#pragma unroll
        for (int s = 0; s < 4; s++) {
#pragma unroll
            for (int half = 0; half < 2; half++) {
                int j = 2 * s + half;
                float bb0 = b1s[j * 8 + tg * 2], bb1 = b1s[j * 8 + tg * 2 + 1];
                float x0 = fmaxf(accl[j][0] + bb0, 0.f);
                float x1 = fmaxf(accl[j][1] + bb1, 0.f);
                float x2 = fmaxf(accl[j][2] + bb0, 0.f);
                float x3 = fmaxf(accl[j][3] + bb1, 0.f);
                split2(x0, x1, hfh[s][half * 2],     hfl[s][half * 2]);
                split2(x2, x3, hfh[s][half * 2 + 1], hfl[s][half * 2 + 1]);
            }
        }
    }

    float acc_o[8][4];
#pragma unroll
    for (int j = 0; j < 8; j++)
#pragma unroll
        for (int i = 0; i < 4; i++) acc_o[j][i] = 0.f;
    float s0 = 0.f, s1 = 0.f;

    for (int c = 0; c < 8; c++) {
        CP_WAIT(0);
        __syncthreads();

        if (c + 1 < 8) {
            int cn = c + 1, slot = cn & 1;
            uint32_t wb = sb + SY_W + slot * 18432;
            uint32_t vb = sb + SY_V + slot * 18432;
            cp_tile_async(wb,        (const char*)(g_w2t_hi + cn * 64 * DK), 512, DK * 2, tid, 128);
            cp_tile_async(wb + 9216, (const char*)(g_w2t_lo + cn * 64 * DK), 512, DK * 2, tid, 128);
            cp_tile_async(vb,        (const char*)(g_vh_hi + vh_base + (size_t)cn * 64 * DK), 512, DK * 2, tid, 128);
            cp_tile_async(vb + 9216, (const char*)(g_vh_lo + vh_base + (size_t)cn * 64 * DK), 512, DK * 2, tid, 128);
        }
        CP_COMMIT();

        const uint32_t wb = sb + SY_W + (c & 1) * 18432;
        const uint32_t vb = sb + SY_V + (c & 1) * 18432;

        float accl[8][4];
#pragma unroll
        for (int j = 0; j < 8; j++)
#pragma unroll
            for (int i = 0; i < 4; i++) accl[j][i] = 0.f;
#pragma unroll
        for (int ks = 0; ks < 4; ks++) {
#pragma unroll
            for (int jp = 0; jp < 4; jp++) {
                uint32_t bh0, bh1, bh2, bh3, bl0, bl1, bl2, bl3;
                unsigned bo = bo_n + (unsigned)(jp * 16 * AST * 2) + ks * 32;
                ldsm4(bh0, bh1, bh2, bh3, wb + bo);
                ldsm4(bl0, bl1, bl2, bl3, wb + 9216 + bo);
                mma_bf16(accl[2 * jp],     hfh[ks][0], hfh[ks][1], hfh[ks][2], hfh[ks][3], bh0, bh1);
                mma_bf16(accl[2 * jp],     hfh[ks][0], hfh[ks][1], hfh[ks][2], hfh[ks][3], bl0, bl1);
                mma_bf16(accl[2 * jp],     hfl[ks][0], hfl[ks][1], hfl[ks][2], hfl[ks][3], bh0, bh1);
                mma_bf16(accl[2 * jp + 1], hfh[ks][0], hfh[ks][1], hfh[ks][2], hfh[ks][3], bh2, bh3);
                mma_bf16(accl[2 * jp + 1], hfh[ks][0], hfh[ks][1], hfh[ks][2], hfh[ks][3], bl2, bl3);
                mma_bf16(accl[2 * jp + 1], hfl[ks][0], hfl[ks][1], hfl[ks][2], hfl[ks][3], bh2, bh3);
            }
        }

        uint32_t pfh[4][4], pfl[4][4];
        const int kc = c * 64;
#pragma unroll
        for (int s = 0; s < 4; s++) {
#pragma unroll
            for (int half = 0; half < 2; half++) {
                int j = 2 * s + half;
                int col = kc + j * 8 + tg * 2;
                float bb0 = __ldg(&g_b2p[col]), bb1 = __ldg(&g_b2p[col + 1]);
                float p0 = __expf(fminf(accl[j][0] + bb0, 80.f));
                float p1 = __expf(fminf(accl[j][1] + bb1, 80.f));
                float p2 = __expf(fminf(accl[j][2] + bb0, 80.f));
                float p3 = __expf(fminf(accl[j][3] + bb1, 80.f));
                s0 += p0 + p1;
                s1 += p2 + p3;
                split2(p0, p1, pfh[s][half * 2],     pfl[s][half * 2]);
                split2(p2, p3, pfh[s][half * 2 + 1], pfl[s][half * 2 + 1]);
            }
        }

#pragma unroll
        for (int ks = 0; ks < 4; ks++) {
#pragma unroll
            for (int jp = 0; jp < 4; jp++) {
                uint32_t bh0, bh1, bh2, bh3, bl0, bl1, bl2, bl3;
                unsigned bo = bo_t + (unsigned)(ks * 16 * AST * 2) + jp * 32;
                ldsm4_t(bh0, bh1, bh2, bh3, vb + bo);
                ldsm4_t(bl0, bl1, bl2, bl3, vb + 9216 + bo);
                mma_bf16(acc_o[2 * jp],     pfh[ks][0], pfh[ks][1], pfh[ks][2], pfh[ks][3], bh0, bh1);
                mma_bf16(acc_o[2 * jp],     pfh[ks][0], pfh[ks][1], pfh[ks][2], pfh[ks][3], bl0, bl1);
                mma_bf16(acc_o[2 * jp],     pfl[ks][0], pfl[ks][1], pfl[ks][2], pfl[ks][3], bh0, bh1);
                mma_bf16(acc_o[2 * jp + 1], pfh[ks][0], pfh[ks][1], pfh[ks][2], pfh[ks][3], bh2, bh3);
                mma_bf16(acc_o[2 * jp + 1], pfh[ks][0], pfh[ks][1], pfh[ks][2], pfh[ks][3], bl2, bl3);
                mma_bf16(acc_o[2 * jp + 1], pfl[ks][0], pfl[ks][1], pfl[ks][2], pfl[ks][3], bh2, bh3);
            }
        }
    }

    s0 += __shfl_xor_sync(0xffffffffu, s0, 1);
    s0 += __shfl_xor_sync(0xffffffffu, s0, 2);
    s1 += __shfl_xor_sync(0xffffffffu, s1, 1);
    s1 += __shfl_xor_sync(0xffffffffu, s1, 2);
    const float inv0 = 1.f / s0, inv1 = 1.f / s1;
    const int b = bh >> 2, hh = bh & 3;
#pragma unroll
    for (int rr = 0; rr < 2; rr++) {
        int ml = mw + g + rr * 8;
        if (ml >= nrows) continue;
        float invv = rr ? inv1 : inv0;
        size_t base = ((size_t)(b * LSEQ + r0 + ml)) * FEAT + hh * 64;
#pragma unroll
        for (int j = 0; j < 8; j++) {
            uint32_t hi, lo;
            split2(acc_o[j][rr * 2] * invv, acc_o[j][rr * 2 + 1] * invv, hi, lo);
            *(uint32_t*)(g_pre_hi + base + j * 8 + tg * 2) = hi;
            *(uint32_t*)(g_pre_lo + base + j * 8 + tg * 2) = lo;
        }
    }
}

// ---------------------------------------------------------------------------
// fc + residual + LayerNorm: cp.async pipelined.
// A (all 4 k-chunks) upfront: hi@0 (4x9216), lo@36864. B ring-2 @73728, slot=73728.
// grid 500, block 256, 1 CTA/SM (221.2KB).
// ---------------------------------------------------------------------------
#define FC_A   0
#define FC_B   73728
#define FC_SMEM 221184

__global__ __launch_bounds__(256, 1) void fc_ln_kernel(const float* __restrict__ q,
                                                       const float* __restrict__ lng,
                                                       const float* __restrict__ lnb,
                                                       float* __restrict__ out) {
    extern __shared__ char sm[];
    const uint32_t sb = smem_u32(sm);
    float* partial = (float*)sm;

    const int tid = threadIdx.x;
    const int w = tid >> 5, lane = tid & 31, g = lane >> 2, tg = lane & 3;
    const int m0 = blockIdx.x * 64;
    const int rg = w >> 1;
    const int nh = w & 1;
    const int mw = rg * 16;

    // prologue: A all 4 chunks (G1), B chunk 0 (G2)
#pragma unroll
    for (int kc = 0; kc < 4; kc++) {
        cp_tile_async(sb + FC_A + kc * 9216,
                      (const char*)(g_pre_hi + (size_t)m0 * FEAT + kc * 64), 512, FEAT * 2, tid, 256);
        cp_tile_async(sb + FC_A + 36864 + kc * 9216,
                      (const char*)(g_pre_lo + (size_t)m0 * FEAT + kc * 64), 512, FEAT * 2, tid, 256);
    }
    CP_COMMIT();
    cp_tile_async(sb + FC_B,         (const char*)g_fcwT_hi, 2048, FEAT * 2, tid, 256);
    cp_tile_async(sb + FC_B + 36864, (const char*)g_fcwT_lo, 2048, FEAT * 2, tid, 256);
    CP_COMMIT();

    float acc[16][4];
#pragma unroll
    for (int j = 0; j < 16; j++)
#pragma unroll
        for (int i = 0; i < 4; i++) acc[j][i] = 0.f;

    for (int kc = 0; kc < 4; kc++) {
        CP_WAIT(0);          // A + B(kc) resident (B(kc) prefetched last iter)
        __syncthreads();     // also: slot (kc+1)&1 free — all warps done reading it

        if (kc + 1 < 4) {
            int cn = kc + 1, slot = cn & 1;
            cp_tile_async(sb + FC_B + slot * 73728,
                          (const char*)(g_fcwT_hi + cn * 64), 2048, FEAT * 2, tid, 256);
            cp_tile_async(sb + FC_B + slot * 73728 + 36864,
                          (const char*)(g_fcwT_lo + cn * 64), 2048, FEAT * 2, tid, 256);
        }
        CP_COMMIT();

        const uint32_t aH = sb + FC_A + kc * 9216;
        const uint32_t aL = aH + 36864;
        const uint32_t bB = sb + FC_B + (kc & 1) * 73728;
        const uint32_t bh_base = bB + nh * 128 * (AST * 2);
        const uint32_t bl_base = bh_base + 36864;
        mma_chunk<16>(acc, aH, aL, bh_base, bl_base, mw, lane);
    }
    __syncthreads();         // mma reads done; smem reusable for partials

    float sums[2][2];
#pragma unroll
    for (int rr = 0; rr < 2; rr++) {
        int r = mw + g + rr * 8;
        const float* qrow = q + (size_t)(m0 + r) * FEAT + nh * 128;
        float s = 0.f, s2 = 0.f;
#pragma unroll
        for (int j = 0; j < 16; j++) {
            float2 qq = *(const float2*)(qrow + j * 8 + tg * 2);
            float x0 = acc[j][rr * 2]     + qq.x;
            float x1 = acc[j][rr * 2 + 1] + qq.y;
            acc[j][rr * 2] = x0;
            acc[j][rr * 2 + 1] = x1;
            s += x0 + x1;
            s2 += x0 * x0 + x1 * x1;
        }
        s  += __shfl_xor_sync(0xffffffffu, s, 1);
        s  += __shfl_xor_sync(0xffffffffu, s, 2);
        s2 += __shfl_xor_sync(0xffffffffu, s2, 1);
        s2 += __shfl_xor_sync(0xffffffffu, s2, 2);
        sums[rr][0] = s;
        sums[rr][1] = s2;
        if (tg == 0) {
            partial[(r * 2 + nh) * 2 + 0] = s;
            partial[(r * 2 + nh) * 2 + 1] = s2;
        }
    }
    __syncthreads();

#pragma unroll
    for (int rr = 0; rr < 2; rr++) {
        int r = mw + g + rr * 8;
        float s  = sums[rr][0] + partial[(r * 2 + (nh ^ 1)) * 2 + 0];
        float s2 = sums[rr][1] + partial[(r * 2 + (nh ^ 1)) * 2 + 1];
        float mu = s * (1.f / FEAT);
        float rstd = rsqrtf(s2 * (1.f / FEAT) - mu * mu + 1e-6f);
        float* orow = out + (size_t)(m0 + r) * FEAT + nh * 128;
#pragma unroll
        for (int j = 0; j < 16; j++) {
            int col = nh * 128 + j * 8 + tg * 2;
            float g0 = __ldg(&lng[col]), g1 = __ldg(&lng[col + 1]);
            float bb0 = __ldg(&lnb[col]), bb1 = __ldg(&lnb[col + 1]);
            float2 o;
            o.x = (acc[j][rr * 2]     - mu) * rstd * g0 + bb0;
            o.y = (acc[j][rr * 2 + 1] - mu) * rstd * g1 + bb1;
            *(float2*)(orow + col - nh * 128) = o;
        }
    }
}

// ---------------------------------------------------------------------------
extern "C" void kernel_launch(void* const* d_in, const int* in_sizes, int n_in,
                              void* d_out, int out_size)
{
    (void)in_sizes; (void)n_in; (void)out_size;
    const float* q    = (const float*)d_in[0];
    const float* v    = (const float*)d_in[2];
    const float* w_qs = (const float*)d_in[3];
    const float* w_vs = (const float*)d_in[4];
    const float* w1   = (const float*)d_in[5];
    const float* b1   = (const float*)d_in[6];
    const float* w2   = (const float*)d_in[7];
    const float* b2   = (const float*)d_in[8];
    const float* fcw  = (const float*)d_in[9];
    const float* lng  = (const float*)d_in[10];
    const float* lnb  = (const float*)d_in[11];
    float* out = (float*)d_out;

    cudaFuncSetAttribute(proj_kernel,  cudaFuncAttributeMaxDynamicSharedMemorySize, PROJ_SMEM);
    cudaFuncSetAttribute(synth_kernel, cudaFuncAttributeMaxDynamicSharedMemorySize, SYN_SMEM);
    cudaFuncSetAttribute(fc_ln_kernel, cudaFuncAttributeMaxDynamicSharedMemorySize, FC_SMEM);

    setup_w<<<128, 256>>>(w_qs, w_vs, fcw, w1, w2, b2);
    proj_kernel<<<dim3(BATCH * 8, 2), 256, PROJ_SMEM>>>(q, v);
    synth_kernel<<<dim3(8, BH), 128, SYN_SMEM>>>(b1);
    fc_ln_kernel<<<500, 256, FC_SMEM>>>(q, lng, lnb, out);
}

// round 14
// speedup vs baseline: 1.2671x; 1.2671x over previous
#include <cuda_runtime.h>
#include <cuda_bf16.h>
#include <cstdint>

#define BATCH 64
#define LSEQ  500
#define FEAT  256
#define HEADS 4
#define DK    64
#define BH    (BATCH*HEADS)       // 256
#define MROWS (BATCH*LSEQ)        // 32000
#define LPAD  512
#define AST   72                  // smem row stride (bf16 elems) -> 144B

// ---------------- device scratch ----------------
static __device__ __nv_bfloat16 g_wqsT_hi[FEAT*FEAT], g_wqsT_lo[FEAT*FEAT];
static __device__ __nv_bfloat16 g_wvsT_hi[FEAT*FEAT], g_wvsT_lo[FEAT*FEAT];
static __device__ __nv_bfloat16 g_fcwT_hi[FEAT*FEAT], g_fcwT_lo[FEAT*FEAT];
static __device__ __nv_bfloat16 g_w1t_hi[DK*DK],      g_w1t_lo[DK*DK];
static __device__ __nv_bfloat16 g_w2t_hi[LPAD*DK];                       // single precision B
static __device__ float         g_b2p[LPAD];
static __device__ __nv_bfloat16 g_qh_hi[BH*LSEQ*DK + 1024], g_qh_lo[BH*LSEQ*DK + 1024];
static __device__ __nv_bfloat16 g_vh_hi[BH*LSEQ*DK + 1024], g_vh_lo[BH*LSEQ*DK + 1024]; // [bh][l][d]
static __device__ __nv_bfloat16 g_pre[MROWS*FEAT];                       // single bf16

// ---------------- helpers ----------------
__device__ __forceinline__ uint32_t smem_u32(const void* p) {
    uint32_t a;
    asm("{ .reg .u64 t; cvta.to.shared.u64 t, %1; cvt.u32.u64 %0, t; }" : "=r"(a) : "l"(p));
    return a;
}
__device__ __forceinline__ uint32_t pack2(__nv_bfloat16 a, __nv_bfloat16 b) {
    return (uint32_t)__bfloat16_as_ushort(a) | ((uint32_t)__bfloat16_as_ushort(b) << 16);
}
__device__ __forceinline__ void split1(float x, __nv_bfloat16& h, __nv_bfloat16& l) {
    h = __float2bfloat16(x);
    l = __float2bfloat16(x - __bfloat162float(h));
}
__device__ __forceinline__ void split2(float x0, float x1, uint32_t& hi, uint32_t& lo) {
    __nv_bfloat16 h0, l0, h1, l1;
    split1(x0, h0, l0);
    split1(x1, h1, l1);
    hi = pack2(h0, h1);
    lo = pack2(l0, l1);
}
__device__ __forceinline__ uint32_t cvt2(float x0, float x1) {
    return pack2(__float2bfloat16(x0), __float2bfloat16(x1));
}

__device__ __forceinline__ void mma_bf16(float acc[4], uint32_t a0, uint32_t a1,
                                         uint32_t a2, uint32_t a3,
                                         uint32_t b0, uint32_t b1) {
    asm volatile(
        "mma.sync.aligned.m16n8k16.row.col.f32.bf16.bf16.f32 "
        "{%0,%1,%2,%3}, {%4,%5,%6,%7}, {%8,%9}, {%0,%1,%2,%3};"
        : "+f"(acc[0]), "+f"(acc[1]), "+f"(acc[2]), "+f"(acc[3])
        : "r"(a0), "r"(a1), "r"(a2), "r"(a3), "r"(b0), "r"(b1));
}
__device__ __forceinline__ void ldsm4(uint32_t& r0, uint32_t& r1, uint32_t& r2, uint32_t& r3,
                                      uint32_t addr) {
    asm volatile("ldmatrix.sync.aligned.m8n8.x4.shared.b16 {%0,%1,%2,%3}, [%4];"
                 : "=r"(r0), "=r"(r1), "=r"(r2), "=r"(r3) : "r"(addr));
}
__device__ __forceinline__ void ldsm4_t(uint32_t& r0, uint32_t& r1, uint32_t& r2, uint32_t& r3,
                                        uint32_t addr) {
    asm volatile("ldmatrix.sync.aligned.m8n8.x4.trans.shared.b16 {%0,%1,%2,%3}, [%4];"
                 : "=r"(r0), "=r"(r1), "=r"(r2), "=r"(r3) : "r"(addr));
}

// 3-term chunk (A hi/lo, B hi/lo) — used by proj.
template <int NF>
__device__ __forceinline__ void mma_chunk(float (*acc)[4],
                                          uint32_t aH, uint32_t aL,
                                          uint32_t bH, uint32_t bL,
                                          int mw, int lane) {
    const int r  = lane & 7;
    const int q3 = (lane >> 3) & 1;
    const int q4 = (lane >> 4) & 1;
    const unsigned aoff = (unsigned)(((mw + q3 * 8 + r) * AST + q4 * 8) * 2);
    const unsigned boff = (unsigned)(((q4 * 8 + r) * AST + q3 * 8) * 2);
#pragma unroll
    for (int ks = 0; ks < 4; ks++) {
        uint32_t ah0, ah1, ah2, ah3, al0, al1, al2, al3;
        ldsm4(ah0, ah1, ah2, ah3, aH + aoff + ks * 32);
        ldsm4(al0, al1, al2, al3, aL + aoff + ks * 32);
#pragma unroll
        for (int jp = 0; jp < NF / 2; jp++) {
            uint32_t bh0, bh1, bh2, bh3, bl0, bl1, bl2, bl3;
            unsigned bo = boff + (unsigned)(jp * 16 * AST * 2) + ks * 32;
            ldsm4(bh0, bh1, bh2, bh3, bH + bo);
            ldsm4(bl0, bl1, bl2, bl3, bL + bo);
            mma_bf16(acc[2 * jp],     ah0, ah1, ah2, ah3, bh0, bh1);
            mma_bf16(acc[2 * jp],     ah0, ah1, ah2, ah3, bl0, bl1);
            mma_bf16(acc[2 * jp],     al0, al1, al2, al3, bh0, bh1);
            mma_bf16(acc[2 * jp + 1], ah0, ah1, ah2, ah3, bh2, bh3);
            mma_bf16(acc[2 * jp + 1], ah0, ah1, ah2, ah3, bl2, bl3);
            mma_bf16(acc[2 * jp + 1], al0, al1, al2, al3, bh2, bh3);
        }
    }
}

// 2-term chunk (A single, B hi/lo) — used by fc.
template <int NF>
__device__ __forceinline__ void mma_chunk2(float (*acc)[4],
                                           uint32_t aH,
                                           uint32_t bH, uint32_t bL,
                                           int mw, int lane) {
    const int r  = lane & 7;
    const int q3 = (lane >> 3) & 1;
    const int q4 = (lane >> 4) & 1;
    const unsigned aoff = (unsigned)(((mw + q3 * 8 + r) * AST + q4 * 8) * 2);
    const unsigned boff = (unsigned)(((q4 * 8 + r) * AST + q3 * 8) * 2);
#pragma unroll
    for (int ks = 0; ks < 4; ks++) {
        uint32_t ah0, ah1, ah2, ah3;
        ldsm4(ah0, ah1, ah2, ah3, aH + aoff + ks * 32);
#pragma unroll
        for (int jp = 0; jp < NF / 2; jp++) {
            uint32_t bh0, bh1, bh2, bh3, bl0, bl1, bl2, bl3;
            unsigned bo = boff + (unsigned)(jp * 16 * AST * 2) + ks * 32;
            ldsm4(bh0, bh1, bh2, bh3, bH + bo);
            ldsm4(bl0, bl1, bl2, bl3, bL + bo);
            mma_bf16(acc[2 * jp],     ah0, ah1, ah2, ah3, bh0, bh1);
            mma_bf16(acc[2 * jp],     ah0, ah1, ah2, ah3, bl0, bl1);
            mma_bf16(acc[2 * jp + 1], ah0, ah1, ah2, ah3, bh2, bh3);
            mma_bf16(acc[2 * jp + 1], ah0, ah1, ah2, ah3, bl2, bl3);
        }
    }
}

__device__ __forceinline__ void cp_tile(char* dst, const char* src, int rows,
                                        int valid, int gstride, int tid, int nt) {
    for (int i = tid; i < rows * 8; i += nt) {
        int r = i >> 3, c = (i & 7) << 4;
        uint4 v = make_uint4(0u, 0u, 0u, 0u);
        if (r < valid) v = *(const uint4*)(src + (size_t)r * gstride + c);
        *(uint4*)(dst + r * (AST * 2) + c) = v;
    }
}

__device__ __forceinline__ void cpa16(uint32_t dst, const void* src) {
    asm volatile("cp.async.ca.shared.global [%0], [%1], 16;" :: "r"(dst), "l"(src));
}
#define CP_COMMIT() asm volatile("cp.async.commit_group;" ::: "memory")
#define CP_WAIT(n)  asm volatile("cp.async.wait_group %0;" :: "n"(n) : "memory")

__device__ __forceinline__ void cp_tile_async(uint32_t dst, const char* src,
                                              int rows8, int gstride, int tid, int nt) {
    for (int i = tid; i < rows8; i += nt) {
        int r = i >> 3, c = (i & 7) << 4;
        cpa16(dst + (unsigned)(r * (AST * 2) + c), src + (size_t)r * gstride + c);
    }
}

// ---------------------------------------------------------------------------
__global__ __launch_bounds__(256) void setup_w(const float* __restrict__ w_qs,
                                               const float* __restrict__ w_vs,
                                               const float* __restrict__ fcw,
                                               const float* __restrict__ w1,
                                               const float* __restrict__ w2,
                                               const float* __restrict__ b2) {
    int i0 = blockIdx.x * blockDim.x + threadIdx.x;
    int nt = gridDim.x * blockDim.x;
    for (int t = i0; t < FEAT * FEAT; t += nt) {
        int n = t >> 8, k = t & 255;
        split1(w_qs[k * FEAT + n], g_wqsT_hi[t], g_wqsT_lo[t]);
        split1(w_vs[k * FEAT + n], g_wvsT_hi[t], g_wvsT_lo[t]);
        split1(fcw [k * FEAT + n], g_fcwT_hi[t], g_fcwT_lo[t]);
    }
    for (int t = i0; t < DK * DK; t += nt) {
        int n = t >> 6, k = t & 63;
        split1(w1[k * DK + n], g_w1t_hi[t], g_w1t_lo[t]);
    }
    for (int t = i0; t < LPAD * DK; t += nt) {
        int n = t >> 6, k = t & 63;
        float f = (n < LSEQ) ? w2[k * LSEQ + n] : 0.f;
        g_w2t_hi[t] = __float2bfloat16(f);
    }
    for (int t = i0; t < LPAD; t += nt)
        g_b2p[t] = (t < LSEQ) ? b2[t] : -1e30f;
}

// ---------------------------------------------------------------------------
// proj: merged heads. CTA = 64 rows x 256 cols (all 4 heads). 3-term.
// grid (BATCH*8, 2), block 256, 2 CTAs/SM.
// ---------------------------------------------------------------------------
#define PR_A_HI 0
#define PR_A_LO 9216
#define PR_B_HI 18432
#define PR_B_LO 55296
#define PROJ_SMEM 92160

__global__ __launch_bounds__(256, 2) void proj_kernel(const float* __restrict__ q,
                                                      const float* __restrict__ v) {
    extern __shared__ char sm[];
    const uint32_t sb = smem_u32(sm);
    char* sA_hi = sm + PR_A_HI;
    char* sA_lo = sm + PR_A_LO;

    const int tid = threadIdx.x;
    const int w = tid >> 5, lane = tid & 31, g = lane >> 2, tg = lane & 3;
    const int b = blockIdx.x >> 3, t = blockIdx.x & 7;
    const int which = blockIdx.y;
    const int l0 = t * 64;
    const int nrows = min(64, LSEQ - l0);
    const int m0 = b * LSEQ + l0;
    const int rg = w >> 1;
    const int nh = w & 1;
    const int mw = rg * 16;

    const float* X = which ? v : q;
    const __nv_bfloat16* Wh = which ? g_wvsT_hi : g_wqsT_hi;
    const __nv_bfloat16* Wl = which ? g_wvsT_lo : g_wqsT_lo;
    __nv_bfloat16* Oh = which ? g_vh_hi : g_qh_hi;
    __nv_bfloat16* Ol = which ? g_vh_lo : g_qh_lo;

    float acc[16][4];
#pragma unroll
    for (int j = 0; j < 16; j++)
#pragma unroll
        for (int i = 0; i < 4; i++) acc[j][i] = 0.f;

    const uint32_t bh_base = sb + PR_B_HI + nh * 128 * (AST * 2);
    const uint32_t bl_base = sb + PR_B_LO + nh * 128 * (AST * 2);

    for (int kc = 0; kc < 4; kc++) {
        int k0 = kc * 64;
        __syncthreads();
        for (int i = tid; i < 64 * 16; i += 256) {
            int r = i >> 4, c4 = (i & 15) << 2;
            float4 a = make_float4(0.f, 0.f, 0.f, 0.f);
            if (r < nrows) a = *(const float4*)(X + (size_t)(m0 + r) * FEAT + k0 + c4);
            uint32_t h0, L0, h1, L1;
            split2(a.x, a.y, h0, L0);
            split2(a.z, a.w, h1, L1);
            unsigned off = (unsigned)(r * (AST * 2) + c4 * 2);
            *(uint2*)(sA_hi + off) = make_uint2(h0, h1);
            *(uint2*)(sA_lo + off) = make_uint2(L0, L1);
        }
        cp_tile(sm + PR_B_HI, (const char*)(Wh + k0), 256, 256, FEAT * 2, tid, 256);
        cp_tile(sm + PR_B_LO, (const char*)(Wl + k0), 256, 256, FEAT * 2, tid, 256);
        __syncthreads();
        mma_chunk<16>(acc, sb + PR_A_HI, sb + PR_A_LO, bh_base, bl_base, mw, lane);
    }

#pragma unroll
    for (int rr = 0; rr < 2; rr++) {
        int ml = mw + g + rr * 8;
        if (ml >= nrows) continue;
        int l = l0 + ml;
#pragma unroll
        for (int j = 0; j < 16; j++) {
            int head = nh * 2 + (j >> 3);
            int d = (j & 7) * 8 + tg * 2;
            size_t base = ((size_t)(b * HEADS + head) * LSEQ + l) * DK + d;
            uint32_t hi, lo;
            split2(acc[j][rr * 2], acc[j][rr * 2 + 1], hi, lo);
            *(uint32_t*)(Oh + base) = hi;
            *(uint32_t*)(Ol + base) = lo;
        }
    }
}

// ---------------------------------------------------------------------------
// synth: M-tile 64, 128 threads, 3 CTAs/SM. Phase-1 full 3-term.
// Mainloop: logits 1-term (hid_hi x w2_hi), out 2-term (P_hi x (V_hi+V_lo)).
// Ring slot = W 9216 + V 18432 = 27648; 2 slots; b1 at end. smem 55.6KB.
// ---------------------------------------------------------------------------
#define SY_SLOT 27648
#define SY_B1   (2*SY_SLOT)
#define SYN_SMEM (2*SY_SLOT + 256)

__global__ __launch_bounds__(128, 3) void synth_kernel(const float* __restrict__ b1) {
    extern __shared__ char sm[];
    const uint32_t sb = smem_u32(sm);
    float* b1s = (float*)(sm + SY_B1);

    const int tid = threadIdx.x;
    const int w = tid >> 5, lane = tid & 31, g = lane >> 2, tg = lane & 3;
    const int bh = blockIdx.y;
    const int r0 = blockIdx.x * 64;
    const int nrows = min(64, LSEQ - r0);
    const int mw = w * 16;

    const int r7 = lane & 7;
    const int q3 = (lane >> 3) & 1;
    const int q4 = (lane >> 4) & 1;
    const unsigned bo_n = (unsigned)(((q4 * 8 + r7) * AST + q3 * 8) * 2);
    const unsigned bo_t = (unsigned)(((q3 * 8 + r7) * AST + q4 * 8) * 2);

    const size_t vh_base = (size_t)bh * LSEQ * DK;
    // w1 parks in slot 1's V area (18432 bytes): safe until chunk-1 prefetch (iter 0)
    const uint32_t w1b = sb + SY_SLOT + 9216;

    // G0: w1 (hi+lo)
    cp_tile_async(w1b,        (const char*)g_w1t_hi, 512, DK * 2, tid, 128);
    cp_tile_async(w1b + 9216, (const char*)g_w1t_lo, 512, DK * 2, tid, 128);
    CP_COMMIT();
    // G1: chunk 0 -> slot 0 (w2 hi, vh hi+lo)
    cp_tile_async(sb,                (const char*)g_w2t_hi, 512, DK * 2, tid, 128);
    cp_tile_async(sb + 9216,         (const char*)(g_vh_hi + vh_base), 512, DK * 2, tid, 128);
    cp_tile_async(sb + 18432,        (const char*)(g_vh_lo + vh_base), 512, DK * 2, tid, 128);
    CP_COMMIT();
    if (tid < 64) b1s[tid] = b1[tid];

    // qh A-fragments direct from gmem (rows warp-private)
    uint32_t qfh[4][4], qfl[4][4];
    {
        const size_t row0 = (size_t)bh * LSEQ + r0 + mw + g;
        const __nv_bfloat16* p0h = g_qh_hi + row0 * DK;
        const __nv_bfloat16* p1h = p0h + 8 * DK;
        const __nv_bfloat16* p0l = g_qh_lo + row0 * DK;
        const __nv_bfloat16* p1l = p0l + 8 * DK;
#pragma unroll
        for (int ks = 0; ks < 4; ks++) {
            int col = ks * 16 + tg * 2;
            qfh[ks][0] = *(const uint32_t*)(p0h + col);
            qfh[ks][1] = *(const uint32_t*)(p1h + col);
            qfh[ks][2] = *(const uint32_t*)(p0h + col + 8);
            qfh[ks][3] = *(const uint32_t*)(p1h + col + 8);
            qfl[ks][0] = *(const uint32_t*)(p0l + col);
            qfl[ks][1] = *(const uint32_t*)(p1l + col);
            qfl[ks][2] = *(const uint32_t*)(p0l + col + 8);
            qfl[ks][3] = *(const uint32_t*)(p1l + col + 8);
        }
    }

    CP_WAIT(1);              // w1 resident
    __syncthreads();

    // phase 1 (3-term): hid = relu(qh@w1 + b1) -> single-bf16 A-fragments hf
    uint32_t hf[4][4];
    {
        float accl[8][4];
#pragma unroll
        for (int j = 0; j < 8; j++)
#pragma unroll
            for (int i = 0; i < 4; i++) accl[j][i] = 0.f;
#pragma unroll
        for (int ks = 0; ks < 4; ks++) {
#pragma unroll
            for (int jp = 0; jp < 4; jp++) {
                uint32_t bh0, bh1, bh2, bh3, bl0, bl1, bl2, bl3;
                unsigned bo = bo_n + (unsigned)(jp * 16 * AST * 2) + ks * 32;
                ldsm4(bh0, bh1, bh2, bh3, w1b + bo);
                ldsm4(bl0, bl1, bl2, bl3, w1b + 9216 + bo);
                mma_bf16(accl[2 * jp],     qfh[ks][0], qfh[ks][1], qfh[ks][2], qfh[ks][3], bh0, bh1);
                mma_bf16(accl[2 * jp],     qfh[ks][0], qfh[ks][1], qfh[ks][2], qfh[ks][3], bl0, bl1);
                mma_bf16(accl[2 * jp],     qfl[ks][0], qfl[ks][1], qfl[ks][2], qfl[ks][3], bh0, bh1);
                mma_bf16(accl[2 * jp + 1], qfh[ks][0], qfh[ks][1], qfh[ks][2], qfh[ks][3], bh2, bh3);
                mma_bf16(accl[2 * jp + 1], qfh[ks][0], qfh[ks][1], qfh[ks][2], qfh[ks][3], bl2, bl3);
                mma_bf16(accl[2 * jp + 1], qfl[ks][0], qfl[ks][1], qfl[ks][2], qfl[ks][3], bh2, bh3);
            }
        }
#pragma unroll
        for (int s = 0; s < 4; s++) {
#pragma unroll
            for (int half = 0; half < 2; half++) {
                int j = 2 * s + half;
                float bb0 = b1s[j * 8 + tg * 2], bb1 = b1s[j * 8 + tg * 2 + 1];
                float x0 = fmaxf(accl[j][0] + bb0, 0.f);
                float x1 = fmaxf(accl[j][1] + bb1, 0.f);
                float x2 = fmaxf(accl[j][2] + bb0, 0.f);
                float x3 = fmaxf(accl[j][3] + bb1, 0.f);
                hf[s][half * 2]     = cvt2(x0, x1);
                hf[s][half * 2 + 1] = cvt2(x2, x3);
            }
        }
    }

    float acc_o[8][4];
#pragma unroll
    for (int j = 0; j < 8; j++)
#pragma unroll
        for (int i = 0; i < 4; i++) acc_o[j][i] = 0.f;
    float s0 = 0.f, s1 = 0.f;

    for (int c = 0; c < 8; c++) {
        CP_WAIT(0);
        __syncthreads();

        if (c + 1 < 8) {
            int cn = c + 1;
            uint32_t slot = sb + (cn & 1) * SY_SLOT;
            cp_tile_async(slot,         (const char*)(g_w2t_hi + cn * 64 * DK), 512, DK * 2, tid, 128);
            cp_tile_async(slot + 9216,  (const char*)(g_vh_hi + vh_base + (size_t)cn * 64 * DK), 512, DK * 2, tid, 128);
            cp_tile_async(slot + 18432, (const char*)(g_vh_lo + vh_base + (size_t)cn * 64 * DK), 512, DK * 2, tid, 128);
        }
        CP_COMMIT();

        const uint32_t wb  = sb + (c & 1) * SY_SLOT;
        const uint32_t vbh = wb + 9216;
        const uint32_t vbl = wb + 18432;

        // logits(c): 1-term (hid_hi x w2_hi)
        float accl[8][4];
#pragma unroll
        for (int j = 0; j < 8; j++)
#pragma unroll
            for (int i = 0; i < 4; i++) accl[j][i] = 0.f;
#pragma unroll
        for (int ks = 0; ks < 4; ks++) {
#pragma unroll
            for (int jp = 0; jp < 4; jp++) {
                uint32_t bh0, bh1, bh2, bh3;
                unsigned bo = bo_n + (unsigned)(jp * 16 * AST * 2) + ks * 32;
                ldsm4(bh0, bh1, bh2, bh3, wb + bo);
                mma_bf16(accl[2 * jp],     hf[ks][0], hf[ks][1], hf[ks][2], hf[ks][3], bh0, bh1);
                mma_bf16(accl[2 * jp + 1], hf[ks][0], hf[ks][1], hf[ks][2], hf[ks][3], bh2, bh3);
            }
        }

        // exp(c): single-bf16 P fragments
        uint32_t pf[4][4];
        const int kc = c * 64;
#pragma unroll
        for (int s = 0; s < 4; s++) {
#pragma unroll
            for (int half = 0; half < 2; half++) {
                int j = 2 * s + half;
                int col = kc + j * 8 + tg * 2;
                float bb0 = __ldg(&g_b2p[col]), bb1 = __ldg(&g_b2p[col + 1]);
                float p0 = __expf(fminf(accl[j][0] + bb0, 80.f));
                float p1 = __expf(fminf(accl[j][1] + bb1, 80.f));
                float p2 = __expf(fminf(accl[j][2] + bb0, 80.f));
                float p3 = __expf(fminf(accl[j][3] + bb1, 80.f));
                s0 += p0 + p1;
                s1 += p2 + p3;
                pf[s][half * 2]     = cvt2(p0, p1);
                pf[s][half * 2 + 1] = cvt2(p2, p3);
            }
        }

        // out(c): 2-term (P_hi x (V_hi + V_lo))
#pragma unroll
        for (int ks = 0; ks < 4; ks++) {
#pragma unroll
            for (int jp = 0; jp < 4; jp++) {
                uint32_t bh0, bh1, bh2, bh3, bl0, bl1, bl2, bl3;
                unsigned bo = bo_t + (unsigned)(ks * 16 * AST * 2) + jp * 32;
                ldsm4_t(bh0, bh1, bh2, bh3, vbh + bo);
                ldsm4_t(bl0, bl1, bl2, bl3, vbl + bo);
                mma_bf16(acc_o[2 * jp],     pf[ks][0], pf[ks][1], pf[ks][2], pf[ks][3], bh0, bh1);
                mma_bf16(acc_o[2 * jp],     pf[ks][0], pf[ks][1], pf[ks][2], pf[ks][3], bl0, bl1);
                mma_bf16(acc_o[2 * jp + 1], pf[ks][0], pf[ks][1], pf[ks][2], pf[ks][3], bh2, bh3);
                mma_bf16(acc_o[2 * jp + 1], pf[ks][0], pf[ks][1], pf[ks][2], pf[ks][3], bl2, bl3);
            }
        }
    }

    s0 += __shfl_xor_sync(0xffffffffu, s0, 1);
    s0 += __shfl_xor_sync(0xffffffffu, s0, 2);
    s1 += __shfl_xor_sync(0xffffffffu, s1, 1);
    s1 += __shfl_xor_sync(0xffffffffu, s1, 2);
    const float inv0 = 1.f / s0, inv1 = 1.f / s1;
    const int b = bh >> 2, hh = bh & 3;
#pragma unroll
    for (int rr = 0; rr < 2; rr++) {
        int ml = mw + g + rr * 8;
        if (ml >= nrows) continue;
        float invv = rr ? inv1 : inv0;
        size_t base = ((size_t)(b * LSEQ + r0 + ml)) * FEAT + hh * 64;
#pragma unroll
        for (int j = 0; j < 8; j++) {
            *(uint32_t*)(g_pre + base + j * 8 + tg * 2) =
                cvt2(acc_o[j][rr * 2] * invv, acc_o[j][rr * 2 + 1] * invv);
        }
    }
}

// ---------------------------------------------------------------------------
// fc + residual + LayerNorm. A single bf16 (2-term mma), B split.
// grid 500, block 256, 64 rows/CTA, 2 CTAs/SM (83KB).
// ---------------------------------------------------------------------------
#define FC_A    0
#define FC_B_HI 9216
#define FC_B_LO 46080
#define FC_SMEM 82944

__global__ __launch_bounds__(256, 2) void fc_ln_kernel(const float* __restrict__ q,
                                                       const float* __restrict__ lng,
                                                       const float* __restrict__ lnb,
                                                       float* __restrict__ out) {
    extern __shared__ char sm[];
    const uint32_t sb = smem_u32(sm);
    float* partial = (float*)sm;

    const int tid = threadIdx.x;
    const int w = tid >> 5, lane = tid & 31, g = lane >> 2, tg = lane & 3;
    const int m0 = blockIdx.x * 64;
    const int rg = w >> 1;
    const int nh = w & 1;
    const int mw = rg * 16;

    float acc[16][4];
#pragma unroll
    for (int j = 0; j < 16; j++)
#pragma unroll
        for (int i = 0; i < 4; i++) acc[j][i] = 0.f;

    const uint32_t bh_base = sb + FC_B_HI + nh * 128 * (AST * 2);
    const uint32_t bl_base = sb + FC_B_LO + nh * 128 * (AST * 2);

    for (int kc = 0; kc < 4; kc++) {
        int k0 = kc * 64;
        __syncthreads();
        cp_tile(sm + FC_A,    (const char*)(g_pre + (size_t)m0 * FEAT + k0), 64, 64, FEAT * 2, tid, 256);
        cp_tile(sm + FC_B_HI, (const char*)(g_fcwT_hi + k0), 256, 256, FEAT * 2, tid, 256);
        cp_tile(sm + FC_B_LO, (const char*)(g_fcwT_lo + k0), 256, 256, FEAT * 2, tid, 256);
        __syncthreads();
        mma_chunk2<16>(acc, sb + FC_A, bh_base, bl_base, mw, lane);
    }
    __syncthreads();

    float sums[2][2];
#pragma unroll
    for (int rr = 0; rr < 2; rr++) {
        int r = mw + g + rr * 8;
        const float* qrow = q + (size_t)(m0 + r) * FEAT + nh * 128;
        float s = 0.f, s2 = 0.f;
#pragma unroll
        for (int j = 0; j < 16; j++) {
            float2 qq = *(const float2*)(qrow + j * 8 + tg * 2);
            float x0 = acc[j][rr * 2]     + qq.x;
            float x1 = acc[j][rr * 2 + 1] + qq.y;
            acc[j][rr * 2] = x0;
            acc[j][rr * 2 + 1] = x1;
            s += x0 + x1;
            s2 += x0 * x0 + x1 * x1;
        }
        s  += __shfl_xor_sync(0xffffffffu, s, 1);
        s  += __shfl_xor_sync(0xffffffffu, s, 2);
        s2 += __shfl_xor_sync(0xffffffffu, s2, 1);
        s2 += __shfl_xor_sync(0xffffffffu, s2, 2);
        sums[rr][0] = s;
        sums[rr][1] = s2;
        if (tg == 0) {
            partial[(r * 2 + nh) * 2 + 0] = s;
            partial[(r * 2 + nh) * 2 + 1] = s2;
        }
    }
    __syncthreads();

#pragma unroll
    for (int rr = 0; rr < 2; rr++) {
        int r = mw + g + rr * 8;
        float s  = sums[rr][0] + partial[(r * 2 + (nh ^ 1)) * 2 + 0];
        float s2 = sums[rr][1] + partial[(r * 2 + (nh ^ 1)) * 2 + 1];
        float mu = s * (1.f / FEAT);
        float rstd = rsqrtf(s2 * (1.f / FEAT) - mu * mu + 1e-6f);
        float* orow = out + (size_t)(m0 + r) * FEAT + nh * 128;
#pragma unroll
        for (int j = 0; j < 16; j++) {
            int col = nh * 128 + j * 8 + tg * 2;
            float g0 = __ldg(&lng[col]), g1 = __ldg(&lng[col + 1]);
            float bb0 = __ldg(&lnb[col]), bb1 = __ldg(&lnb[col + 1]);
            float2 o;
            o.x = (acc[j][rr * 2]     - mu) * rstd * g0 + bb0;
            o.y = (acc[j][rr * 2 + 1] - mu) * rstd * g1 + bb1;
            *(float2*)(orow + col - nh * 128) = o;
        }
    }
}

// ---------------------------------------------------------------------------
extern "C" void kernel_launch(void* const* d_in, const int* in_sizes, int n_in,
                              void* d_out, int out_size)
{
    (void)in_sizes; (void)n_in; (void)out_size;
    const float* q    = (const float*)d_in[0];
    const float* v    = (const float*)d_in[2];
    const float* w_qs = (const float*)d_in[3];
    const float* w_vs = (const float*)d_in[4];
    const float* w1   = (const float*)d_in[5];
    const float* b1   = (const float*)d_in[6];
    const float* w2   = (const float*)d_in[7];
    const float* b2   = (const float*)d_in[8];
    const float* fcw  = (const float*)d_in[9];
    const float* lng  = (const float*)d_in[10];
    const float* lnb  = (const float*)d_in[11];
    float* out = (float*)d_out;

    cudaFuncSetAttribute(proj_kernel,  cudaFuncAttributeMaxDynamicSharedMemorySize, PROJ_SMEM);
    cudaFuncSetAttribute(synth_kernel, cudaFuncAttributeMaxDynamicSharedMemorySize, SYN_SMEM);
    cudaFuncSetAttribute(fc_ln_kernel, cudaFuncAttributeMaxDynamicSharedMemorySize, FC_SMEM);

    setup_w<<<128, 256>>>(w_qs, w_vs, fcw, w1, w2, b2);
    proj_kernel<<<dim3(BATCH * 8, 2), 256, PROJ_SMEM>>>(q, v);
    synth_kernel<<<dim3(8, BH), 128, SYN_SMEM>>>(b1);
    fc_ln_kernel<<<500, 256, FC_SMEM>>>(q, lng, lnb, out);
}

// round 15
// speedup vs baseline: 1.5389x; 1.2145x over previous
#include <cuda_runtime.h>
#include <cuda_bf16.h>
#include <cstdint>

#define BATCH 64
#define LSEQ  500
#define FEAT  256
#define HEADS 4
#define DK    64
#define BH    (BATCH*HEADS)       // 256
#define MROWS (BATCH*LSEQ)        // 32000
#define LPAD  512
#define AST   72                  // smem row stride (bf16 elems) -> 144B

// ---------------- device scratch ----------------
static __device__ __nv_bfloat16 g_wqsT_hi[FEAT*FEAT], g_wqsT_lo[FEAT*FEAT];
static __device__ __nv_bfloat16 g_wvsT_hi[FEAT*FEAT], g_wvsT_lo[FEAT*FEAT];
static __device__ __nv_bfloat16 g_fcwT_hi[FEAT*FEAT], g_fcwT_lo[FEAT*FEAT];
static __device__ __nv_bfloat16 g_w1t_hi[DK*DK],      g_w1t_lo[DK*DK];
static __device__ __nv_bfloat16 g_w2t[LPAD*DK];                          // single bf16
static __device__ float         g_b2p[LPAD];
static __device__ __nv_bfloat16 g_qh[BH*LSEQ*DK + 1024];                 // single bf16
static __device__ __nv_bfloat16 g_vh[BH*LSEQ*DK + 1024];                 // single bf16 [bh][l][d]
static __device__ __nv_bfloat16 g_pre[MROWS*FEAT];                       // single bf16

// ---------------- helpers ----------------
__device__ __forceinline__ uint32_t smem_u32(const void* p) {
    uint32_t a;
    asm("{ .reg .u64 t; cvta.to.shared.u64 t, %1; cvt.u32.u64 %0, t; }" : "=r"(a) : "l"(p));
    return a;
}
__device__ __forceinline__ uint32_t pack2(__nv_bfloat16 a, __nv_bfloat16 b) {
    return (uint32_t)__bfloat16_as_ushort(a) | ((uint32_t)__bfloat16_as_ushort(b) << 16);
}
__device__ __forceinline__ void split1(float x, __nv_bfloat16& h, __nv_bfloat16& l) {
    h = __float2bfloat16(x);
    l = __float2bfloat16(x - __bfloat162float(h));
}
__device__ __forceinline__ uint32_t cvt2(float x0, float x1) {
    return pack2(__float2bfloat16(x0), __float2bfloat16(x1));
}

__device__ __forceinline__ void mma_bf16(float acc[4], uint32_t a0, uint32_t a1,
                                         uint32_t a2, uint32_t a3,
                                         uint32_t b0, uint32_t b1) {
    asm volatile(
        "mma.sync.aligned.m16n8k16.row.col.f32.bf16.bf16.f32 "
        "{%0,%1,%2,%3}, {%4,%5,%6,%7}, {%8,%9}, {%0,%1,%2,%3};"
        : "+f"(acc[0]), "+f"(acc[1]), "+f"(acc[2]), "+f"(acc[3])
        : "r"(a0), "r"(a1), "r"(a2), "r"(a3), "r"(b0), "r"(b1));
}
__device__ __forceinline__ void ldsm4(uint32_t& r0, uint32_t& r1, uint32_t& r2, uint32_t& r3,
                                      uint32_t addr) {
    asm volatile("ldmatrix.sync.aligned.m8n8.x4.shared.b16 {%0,%1,%2,%3}, [%4];"
                 : "=r"(r0), "=r"(r1), "=r"(r2), "=r"(r3) : "r"(addr));
}
__device__ __forceinline__ void ldsm4_t(uint32_t& r0, uint32_t& r1, uint32_t& r2, uint32_t& r3,
                                        uint32_t addr) {
    asm volatile("ldmatrix.sync.aligned.m8n8.x4.trans.shared.b16 {%0,%1,%2,%3}, [%4];"
                 : "=r"(r0), "=r"(r1), "=r"(r2), "=r"(r3) : "r"(addr));
}

// 2-term chunk (A single, B hi/lo) — proj and fc.
template <int NF>
__device__ __forceinline__ void mma_chunk2(float (*acc)[4],
                                           uint32_t aH,
                                           uint32_t bH, uint32_t bL,
                                           int mw, int lane) {
    const int r  = lane & 7;
    const int q3 = (lane >> 3) & 1;
    const int q4 = (lane >> 4) & 1;
    const unsigned aoff = (unsigned)(((mw + q3 * 8 + r) * AST + q4 * 8) * 2);
    const unsigned boff = (unsigned)(((q4 * 8 + r) * AST + q3 * 8) * 2);
#pragma unroll
    for (int ks = 0; ks < 4; ks++) {
        uint32_t ah0, ah1, ah2, ah3;
        ldsm4(ah0, ah1, ah2, ah3, aH + aoff + ks * 32);
#pragma unroll
        for (int jp = 0; jp < NF / 2; jp++) {
            uint32_t bh0, bh1, bh2, bh3, bl0, bl1, bl2, bl3;
            unsigned bo = boff + (unsigned)(jp * 16 * AST * 2) + ks * 32;
            ldsm4(bh0, bh1, bh2, bh3, bH + bo);
            ldsm4(bl0, bl1, bl2, bl3, bL + bo);
            mma_bf16(acc[2 * jp],     ah0, ah1, ah2, ah3, bh0, bh1);
            mma_bf16(acc[2 * jp],     ah0, ah1, ah2, ah3, bl0, bl1);
            mma_bf16(acc[2 * jp + 1], ah0, ah1, ah2, ah3, bh2, bh3);
            mma_bf16(acc[2 * jp + 1], ah0, ah1, ah2, ah3, bl2, bl3);
        }
    }
}

__device__ __forceinline__ void cp_tile(char* dst, const char* src, int rows,
                                        int valid, int gstride, int tid, int nt) {
    for (int i = tid; i < rows * 8; i += nt) {
        int r = i >> 3, c = (i & 7) << 4;
        uint4 v = make_uint4(0u, 0u, 0u, 0u);
        if (r < valid) v = *(const uint4*)(src + (size_t)r * gstride + c);
        *(uint4*)(dst + r * (AST * 2) + c) = v;
    }
}

__device__ __forceinline__ void cpa16(uint32_t dst, const void* src) {
    asm volatile("cp.async.ca.shared.global [%0], [%1], 16;" :: "r"(dst), "l"(src));
}
#define CP_COMMIT() asm volatile("cp.async.commit_group;" ::: "memory")
#define CP_WAIT(n)  asm volatile("cp.async.wait_group %0;" :: "n"(n) : "memory")

__device__ __forceinline__ void cp_tile_async(uint32_t dst, const char* src,
                                              int rows8, int gstride, int tid, int nt) {
    for (int i = tid; i < rows8; i += nt) {
        int r = i >> 3, c = (i & 7) << 4;
        cpa16(dst + (unsigned)(r * (AST * 2) + c), src + (size_t)r * gstride + c);
    }
}

// ---------------------------------------------------------------------------
__global__ __launch_bounds__(256) void setup_w(const float* __restrict__ w_qs,
                                               const float* __restrict__ w_vs,
                                               const float* __restrict__ fcw,
                                               const float* __restrict__ w1,
                                               const float* __restrict__ w2,
                                               const float* __restrict__ b2) {
    int i0 = blockIdx.x * blockDim.x + threadIdx.x;
    int nt = gridDim.x * blockDim.x;
    for (int t = i0; t < FEAT * FEAT; t += nt) {
        int n = t >> 8, k = t & 255;
        split1(w_qs[k * FEAT + n], g_wqsT_hi[t], g_wqsT_lo[t]);
        split1(w_vs[k * FEAT + n], g_wvsT_hi[t], g_wvsT_lo[t]);
        split1(fcw [k * FEAT + n], g_fcwT_hi[t], g_fcwT_lo[t]);
    }
    for (int t = i0; t < DK * DK; t += nt) {
        int n = t >> 6, k = t & 63;
        split1(w1[k * DK + n], g_w1t_hi[t], g_w1t_lo[t]);
    }
    for (int t = i0; t < LPAD * DK; t += nt) {
        int n = t >> 6, k = t & 63;
        float f = (n < LSEQ) ? w2[k * LSEQ + n] : 0.f;
        g_w2t[t] = __float2bfloat16(f);
    }
    for (int t = i0; t < LPAD; t += nt)
        g_b2p[t] = (t < LSEQ) ? b2[t] : -1e30f;
}

// ---------------------------------------------------------------------------
// proj: merged heads, 2-term (A single bf16, B hi/lo). CTA = 64 rows x 256 cols.
// grid (BATCH*8, 2), block 256, 2 CTAs/SM (83KB).
// ---------------------------------------------------------------------------
#define PR_A    0
#define PR_B_HI 9216
#define PR_B_LO 46080
#define PROJ_SMEM 82944

__global__ __launch_bounds__(256, 2) void proj_kernel(const float* __restrict__ q,
                                                      const float* __restrict__ v) {
    extern __shared__ char sm[];
    const uint32_t sb = smem_u32(sm);
    char* sA = sm + PR_A;

    const int tid = threadIdx.x;
    const int w = tid >> 5, lane = tid & 31, g = lane >> 2, tg = lane & 3;
    const int b = blockIdx.x >> 3, t = blockIdx.x & 7;
    const int which = blockIdx.y;
    const int l0 = t * 64;
    const int nrows = min(64, LSEQ - l0);
    const int m0 = b * LSEQ + l0;
    const int rg = w >> 1;
    const int nh = w & 1;
    const int mw = rg * 16;

    const float* X = which ? v : q;
    const __nv_bfloat16* Wh = which ? g_wvsT_hi : g_wqsT_hi;
    const __nv_bfloat16* Wl = which ? g_wvsT_lo : g_wqsT_lo;
    __nv_bfloat16* O = which ? g_vh : g_qh;

    float acc[16][4];
#pragma unroll
    for (int j = 0; j < 16; j++)
#pragma unroll
        for (int i = 0; i < 4; i++) acc[j][i] = 0.f;

    const uint32_t bh_base = sb + PR_B_HI + nh * 128 * (AST * 2);
    const uint32_t bl_base = sb + PR_B_LO + nh * 128 * (AST * 2);

    for (int kc = 0; kc < 4; kc++) {
        int k0 = kc * 64;
        __syncthreads();
        // A: fp32 load, round to single bf16
        for (int i = tid; i < 64 * 16; i += 256) {
            int r = i >> 4, c4 = (i & 15) << 2;
            float4 a = make_float4(0.f, 0.f, 0.f, 0.f);
            if (r < nrows) a = *(const float4*)(X + (size_t)(m0 + r) * FEAT + k0 + c4);
            unsigned off = (unsigned)(r * (AST * 2) + c4 * 2);
            *(uint2*)(sA + off) = make_uint2(cvt2(a.x, a.y), cvt2(a.z, a.w));
        }
        cp_tile(sm + PR_B_HI, (const char*)(Wh + k0), 256, 256, FEAT * 2, tid, 256);
        cp_tile(sm + PR_B_LO, (const char*)(Wl + k0), 256, 256, FEAT * 2, tid, 256);
        __syncthreads();
        mma_chunk2<16>(acc, sb + PR_A, bh_base, bl_base, mw, lane);
    }

#pragma unroll
    for (int rr = 0; rr < 2; rr++) {
        int ml = mw + g + rr * 8;
        if (ml >= nrows) continue;
        int l = l0 + ml;
#pragma unroll
        for (int j = 0; j < 16; j++) {
            int head = nh * 2 + (j >> 3);
            int d = (j & 7) * 8 + tg * 2;
            size_t base = ((size_t)(b * HEADS + head) * LSEQ + l) * DK + d;
            *(uint32_t*)(O + base) = cvt2(acc[j][rr * 2], acc[j][rr * 2 + 1]);
        }
    }
}

// ---------------------------------------------------------------------------
// synth: M-tile 64, 128 threads, 4 CTAs/SM (37.1KB).
// Phase-1 2-term (qf single x w1 hi/lo); logits 1-term; out 1-term.
// Slot = w2 9216 + vh 9216 = 18432; 2 slots; b1 at end.
// ---------------------------------------------------------------------------
#define SY_SLOT 18432
#define SY_B1   (2*SY_SLOT)
#define SYN_SMEM (2*SY_SLOT + 256)

__global__ __launch_bounds__(128, 4) void synth_kernel(const float* __restrict__ b1) {
    extern __shared__ char sm[];
    const uint32_t sb = smem_u32(sm);
    float* b1s = (float*)(sm + SY_B1);

    const int tid = threadIdx.x;
    const int w = tid >> 5, lane = tid & 31, g = lane >> 2, tg = lane & 3;
    const int bh = blockIdx.y;
    const int r0 = blockIdx.x * 64;
    const int nrows = min(64, LSEQ - r0);
    const int mw = w * 16;

    const int r7 = lane & 7;
    const int q3 = (lane >> 3) & 1;
    const int q4 = (lane >> 4) & 1;
    const unsigned bo_n = (unsigned)(((q4 * 8 + r7) * AST + q3 * 8) * 2);
    const unsigned bo_t = (unsigned)(((q3 * 8 + r7) * AST + q4 * 8) * 2);

    const size_t vh_base = (size_t)bh * LSEQ * DK;
    // w1 (hi@+0, lo@+9216) parks in slot 1; overwritten by chunk-1 prefetch (iter 0)
    const uint32_t w1b = sb + SY_SLOT;

    // G0: w1
    cp_tile_async(w1b,        (const char*)g_w1t_hi, 512, DK * 2, tid, 128);
    cp_tile_async(w1b + 9216, (const char*)g_w1t_lo, 512, DK * 2, tid, 128);
    CP_COMMIT();
    // G1: chunk 0 -> slot 0
    cp_tile_async(sb,        (const char*)g_w2t, 512, DK * 2, tid, 128);
    cp_tile_async(sb + 9216, (const char*)(g_vh + vh_base), 512, DK * 2, tid, 128);
    CP_COMMIT();
    if (tid < 64) b1s[tid] = b1[tid];

    // qh A-fragments direct from gmem (single bf16; rows warp-private)
    uint32_t qf[4][4];
    {
        const size_t row0 = (size_t)bh * LSEQ + r0 + mw + g;
        const __nv_bfloat16* p0 = g_qh + row0 * DK;
        const __nv_bfloat16* p1 = p0 + 8 * DK;
#pragma unroll
        for (int ks = 0; ks < 4; ks++) {
            int col = ks * 16 + tg * 2;
            qf[ks][0] = *(const uint32_t*)(p0 + col);
            qf[ks][1] = *(const uint32_t*)(p1 + col);
            qf[ks][2] = *(const uint32_t*)(p0 + col + 8);
            qf[ks][3] = *(const uint32_t*)(p1 + col + 8);
        }
    }

    CP_WAIT(1);              // w1 resident
    __syncthreads();

    // phase 1 (2-term): hid = relu(qh@w1 + b1) -> single-bf16 A-fragments hf
    uint32_t hf[4][4];
    {
        float accl[8][4];
#pragma unroll
        for (int j = 0; j < 8; j++)
#pragma unroll
            for (int i = 0; i < 4; i++) accl[j][i] = 0.f;
#pragma unroll
        for (int ks = 0; ks < 4; ks++) {
#pragma unroll
            for (int jp = 0; jp < 4; jp++) {
                uint32_t bh0, bh1, bh2, bh3, bl0, bl1, bl2, bl3;
                unsigned bo = bo_n + (unsigned)(jp * 16 * AST * 2) + ks * 32;
                ldsm4(bh0, bh1, bh2, bh3, w1b + bo);
                ldsm4(bl0, bl1, bl2, bl3, w1b + 9216 + bo);
                mma_bf16(accl[2 * jp],     qf[ks][0], qf[ks][1], qf[ks][2], qf[ks][3], bh0, bh1);
                mma_bf16(accl[2 * jp],     qf[ks][0], qf[ks][1], qf[ks][2], qf[ks][3], bl0, bl1);
                mma_bf16(accl[2 * jp + 1], qf[ks][0], qf[ks][1], qf[ks][2], qf[ks][3], bh2, bh3);
                mma_bf16(accl[2 * jp + 1], qf[ks][0], qf[ks][1], qf[ks][2], qf[ks][3], bl2, bl3);
            }
        }
#pragma unroll
        for (int s = 0; s < 4; s++) {
#pragma unroll
            for (int half = 0; half < 2; half++) {
                int j = 2 * s + half;
                float bb0 = b1s[j * 8 + tg * 2], bb1 = b1s[j * 8 + tg * 2 + 1];
                hf[s][half * 2]     = cvt2(fmaxf(accl[j][0] + bb0, 0.f),
                                           fmaxf(accl[j][1] + bb1, 0.f));
                hf[s][half * 2 + 1] = cvt2(fmaxf(accl[j][2] + bb0, 0.f),
                                           fmaxf(accl[j][3] + bb1, 0.f));
            }
        }
    }

    float acc_o[8][4];
#pragma unroll
    for (int j = 0; j < 8; j++)
#pragma unroll
        for (int i = 0; i < 4; i++) acc_o[j][i] = 0.f;
    float s0 = 0.f, s1 = 0.f;

    for (int c = 0; c < 8; c++) {
        CP_WAIT(0);
        __syncthreads();

        if (c + 1 < 8) {
            int cn = c + 1;
            uint32_t slot = sb + (cn & 1) * SY_SLOT;
            cp_tile_async(slot,        (const char*)(g_w2t + cn * 64 * DK), 512, DK * 2, tid, 128);
            cp_tile_async(slot + 9216, (const char*)(g_vh + vh_base + (size_t)cn * 64 * DK), 512, DK * 2, tid, 128);
        }
        CP_COMMIT();

        const uint32_t wb = sb + (c & 1) * SY_SLOT;
        const uint32_t vb = wb + 9216;

        // logits(c): 1-term
        float accl[8][4];
#pragma unroll
        for (int j = 0; j < 8; j++)
#pragma unroll
            for (int i = 0; i < 4; i++) accl[j][i] = 0.f;
#pragma unroll
        for (int ks = 0; ks < 4; ks++) {
#pragma unroll
            for (int jp = 0; jp < 4; jp++) {
                uint32_t bh0, bh1, bh2, bh3;
                unsigned bo = bo_n + (unsigned)(jp * 16 * AST * 2) + ks * 32;
                ldsm4(bh0, bh1, bh2, bh3, wb + bo);
                mma_bf16(accl[2 * jp],     hf[ks][0], hf[ks][1], hf[ks][2], hf[ks][3], bh0, bh1);
                mma_bf16(accl[2 * jp + 1], hf[ks][0], hf[ks][1], hf[ks][2], hf[ks][3], bh2, bh3);
            }
        }

        // exp(c): single-bf16 P fragments
        uint32_t pf[4][4];
        const int kc = c * 64;
#pragma unroll
        for (int s = 0; s < 4; s++) {
#pragma unroll
            for (int half = 0; half < 2; half++) {
                int j = 2 * s + half;
                int col = kc + j * 8 + tg * 2;
                float bb0 = __ldg(&g_b2p[col]), bb1 = __ldg(&g_b2p[col + 1]);
                float p0 = __expf(fminf(accl[j][0] + bb0, 80.f));
                float p1 = __expf(fminf(accl[j][1] + bb1, 80.f));
                float p2 = __expf(fminf(accl[j][2] + bb0, 80.f));
                float p3 = __expf(fminf(accl[j][3] + bb1, 80.f));
                s0 += p0 + p1;
                s1 += p2 + p3;
                pf[s][half * 2]     = cvt2(p0, p1);
                pf[s][half * 2 + 1] = cvt2(p2, p3);
            }
        }

        // out(c): 1-term (P x V single)
#pragma unroll
        for (int ks = 0; ks < 4; ks++) {
#pragma unroll
            for (int jp = 0; jp < 4; jp++) {
                uint32_t bh0, bh1, bh2, bh3;
                unsigned bo = bo_t + (unsigned)(ks * 16 * AST * 2) + jp * 32;
                ldsm4_t(bh0, bh1, bh2, bh3, vb + bo);
                mma_bf16(acc_o[2 * jp],     pf[ks][0], pf[ks][1], pf[ks][2], pf[ks][3], bh0, bh1);
                mma_bf16(acc_o[2 * jp + 1], pf[ks][0], pf[ks][1], pf[ks][2], pf[ks][3], bh2, bh3);
            }
        }
    }

    s0 += __shfl_xor_sync(0xffffffffu, s0, 1);
    s0 += __shfl_xor_sync(0xffffffffu, s0, 2);
    s1 += __shfl_xor_sync(0xffffffffu, s1, 1);
    s1 += __shfl_xor_sync(0xffffffffu, s1, 2);
    const float inv0 = 1.f / s0, inv1 = 1.f / s1;
    const int b = bh >> 2, hh = bh & 3;
#pragma unroll
    for (int rr = 0; rr < 2; rr++) {
        int ml = mw + g + rr * 8;
        if (ml >= nrows) continue;
        float invv = rr ? inv1 : inv0;
        size_t base = ((size_t)(b * LSEQ + r0 + ml)) * FEAT + hh * 64;
#pragma unroll
        for (int j = 0; j < 8; j++) {
            *(uint32_t*)(g_pre + base + j * 8 + tg * 2) =
                cvt2(acc_o[j][rr * 2] * invv, acc_o[j][rr * 2 + 1] * invv);
        }
    }
}

// ---------------------------------------------------------------------------
// fc + residual + LayerNorm. A single bf16 (2-term mma), B split.
// grid 500, block 256, 64 rows/CTA, 2 CTAs/SM (83KB).
// ---------------------------------------------------------------------------
#define FC_A    0
#define FC_B_HI 9216
#define FC_B_LO 46080
#define FC_SMEM 82944

__global__ __launch_bounds__(256, 2) void fc_ln_kernel(const float* __restrict__ q,
                                                       const float* __restrict__ lng,
                                                       const float* __restrict__ lnb,
                                                       float* __restrict__ out) {
    extern __shared__ char sm[];
    const uint32_t sb = smem_u32(sm);
    float* partial = (float*)sm;

    const int tid = threadIdx.x;
    const int w = tid >> 5, lane = tid & 31, g = lane >> 2, tg = lane & 3;
    const int m0 = blockIdx.x * 64;
    const int rg = w >> 1;
    const int nh = w & 1;
    const int mw = rg * 16;

    float acc[16][4];
#pragma unroll
    for (int j = 0; j < 16; j++)
#pragma unroll
        for (int i = 0; i < 4; i++) acc[j][i] = 0.f;

    const uint32_t bh_base = sb + FC_B_HI + nh * 128 * (AST * 2);
    const uint32_t bl_base = sb + FC_B_LO + nh * 128 * (AST * 2);

    for (int kc = 0; kc < 4; kc++) {
        int k0 = kc * 64;
        __syncthreads();
        cp_tile(sm + FC_A,    (const char*)(g_pre + (size_t)m0 * FEAT + k0), 64, 64, FEAT * 2, tid, 256);
        cp_tile(sm + FC_B_HI, (const char*)(g_fcwT_hi + k0), 256, 256, FEAT * 2, tid, 256);
        cp_tile(sm + FC_B_LO, (const char*)(g_fcwT_lo + k0), 256, 256, FEAT * 2, tid, 256);
        __syncthreads();
        mma_chunk2<16>(acc, sb + FC_A, bh_base, bl_base, mw, lane);
    }
    __syncthreads();

    float sums[2][2];
#pragma unroll
    for (int rr = 0; rr < 2; rr++) {
        int r = mw + g + rr * 8;
        const float* qrow = q + (size_t)(m0 + r) * FEAT + nh * 128;
        float s = 0.f, s2 = 0.f;
#pragma unroll
        for (int j = 0; j < 16; j++) {
            float2 qq = *(const float2*)(qrow + j * 8 + tg * 2);
            float x0 = acc[j][rr * 2]     + qq.x;
            float x1 = acc[j][rr * 2 + 1] + qq.y;
            acc[j][rr * 2] = x0;
            acc[j][rr * 2 + 1] = x1;
            s += x0 + x1;
            s2 += x0 * x0 + x1 * x1;
        }
        s  += __shfl_xor_sync(0xffffffffu, s, 1);
        s  += __shfl_xor_sync(0xffffffffu, s, 2);
        s2 += __shfl_xor_sync(0xffffffffu, s2, 1);
        s2 += __shfl_xor_sync(0xffffffffu, s2, 2);
        sums[rr][0] = s;
        sums[rr][1] = s2;
        if (tg == 0) {
            partial[(r * 2 + nh) * 2 + 0] = s;
            partial[(r * 2 + nh) * 2 + 1] = s2;
        }
    }
    __syncthreads();

#pragma unroll
    for (int rr = 0; rr < 2; rr++) {
        int r = mw + g + rr * 8;
        float s  = sums[rr][0] + partial[(r * 2 + (nh ^ 1)) * 2 + 0];
        float s2 = sums[rr][1] + partial[(r * 2 + (nh ^ 1)) * 2 + 1];
        float mu = s * (1.f / FEAT);
        float rstd = rsqrtf(s2 * (1.f / FEAT) - mu * mu + 1e-6f);
        float* orow = out + (size_t)(m0 + r) * FEAT + nh * 128;
#pragma unroll
        for (int j = 0; j < 16; j++) {
            int col = nh * 128 + j * 8 + tg * 2;
            float g0 = __ldg(&lng[col]), g1 = __ldg(&lng[col + 1]);
            float bb0 = __ldg(&lnb[col]), bb1 = __ldg(&lnb[col + 1]);
            float2 o;
            o.x = (acc[j][rr * 2]     - mu) * rstd * g0 + bb0;
            o.y = (acc[j][rr * 2 + 1] - mu) * rstd * g1 + bb1;
            *(float2*)(orow + col - nh * 128) = o;
        }
    }
}

// ---------------------------------------------------------------------------
extern "C" void kernel_launch(void* const* d_in, const int* in_sizes, int n_in,
                              void* d_out, int out_size)
{
    (void)in_sizes; (void)n_in; (void)out_size;
    const float* q    = (const float*)d_in[0];
    const float* v    = (const float*)d_in[2];
    const float* w_qs = (const float*)d_in[3];
    const float* w_vs = (const float*)d_in[4];
    const float* w1   = (const float*)d_in[5];
    const float* b1   = (const float*)d_in[6];
    const float* w2   = (const float*)d_in[7];
    const float* b2   = (const float*)d_in[8];
    const float* fcw  = (const float*)d_in[9];
    const float* lng  = (const float*)d_in[10];
    const float* lnb  = (const float*)d_in[11];
    float* out = (float*)d_out;

    cudaFuncSetAttribute(proj_kernel,  cudaFuncAttributeMaxDynamicSharedMemorySize, PROJ_SMEM);
    cudaFuncSetAttribute(synth_kernel, cudaFuncAttributeMaxDynamicSharedMemorySize, SYN_SMEM);
    cudaFuncSetAttribute(fc_ln_kernel, cudaFuncAttributeMaxDynamicSharedMemorySize, FC_SMEM);

    setup_w<<<128, 256>>>(w_qs, w_vs, fcw, w1, w2, b2);
    proj_kernel<<<dim3(BATCH * 8, 2), 256, PROJ_SMEM>>>(q, v);
    synth_kernel<<<dim3(8, BH), 128, SYN_SMEM>>>(b1);
    fc_ln_kernel<<<500, 256, FC_SMEM>>>(q, lng, lnb, out);
}

// round 16
// speedup vs baseline: 1.5535x; 1.0095x over previous
#include <cuda_runtime.h>
#include <cuda_bf16.h>
#include <cstdint>

#define BATCH 64
#define LSEQ  500
#define FEAT  256
#define HEADS 4
#define DK    64
#define BH    (BATCH*HEADS)       // 256
#define MROWS (BATCH*LSEQ)        // 32000
#define LPAD  512
#define AST   72                  // smem row stride (bf16 elems) -> 144B

// ---------------- device scratch ----------------
static __device__ __nv_bfloat16 g_wqsT[FEAT*FEAT];                       // single bf16 [n][k]
static __device__ __nv_bfloat16 g_wvsT[FEAT*FEAT];
static __device__ __nv_bfloat16 g_fcwT[FEAT*FEAT];
static __device__ __nv_bfloat16 g_w1t_hi[DK*DK], g_w1t_lo[DK*DK];
static __device__ __nv_bfloat16 g_w2t[LPAD*DK];
static __device__ float         g_b2p[LPAD];
static __device__ __nv_bfloat16 g_qh[BH*LSEQ*DK + 1024];                 // [bh][l][d]
static __device__ __nv_bfloat16 g_vh[BH*LSEQ*DK + 1024];
static __device__ __nv_bfloat16 g_pre[MROWS*FEAT];

// ---------------- helpers ----------------
__device__ __forceinline__ uint32_t smem_u32(const void* p) {
    uint32_t a;
    asm("{ .reg .u64 t; cvta.to.shared.u64 t, %1; cvt.u32.u64 %0, t; }" : "=r"(a) : "l"(p));
    return a;
}
__device__ __forceinline__ uint32_t pack2(__nv_bfloat16 a, __nv_bfloat16 b) {
    return (uint32_t)__bfloat16_as_ushort(a) | ((uint32_t)__bfloat16_as_ushort(b) << 16);
}
__device__ __forceinline__ void split1(float x, __nv_bfloat16& h, __nv_bfloat16& l) {
    h = __float2bfloat16(x);
    l = __float2bfloat16(x - __bfloat162float(h));
}
__device__ __forceinline__ uint32_t cvt2(float x0, float x1) {
    return pack2(__float2bfloat16(x0), __float2bfloat16(x1));
}

__device__ __forceinline__ void mma_bf16(float acc[4], uint32_t a0, uint32_t a1,
                                         uint32_t a2, uint32_t a3,
                                         uint32_t b0, uint32_t b1) {
    asm volatile(
        "mma.sync.aligned.m16n8k16.row.col.f32.bf16.bf16.f32 "
        "{%0,%1,%2,%3}, {%4,%5,%6,%7}, {%8,%9}, {%0,%1,%2,%3};"
        : "+f"(acc[0]), "+f"(acc[1]), "+f"(acc[2]), "+f"(acc[3])
        : "r"(a0), "r"(a1), "r"(a2), "r"(a3), "r"(b0), "r"(b1));
}
__device__ __forceinline__ void ldsm4(uint32_t& r0, uint32_t& r1, uint32_t& r2, uint32_t& r3,
                                      uint32_t addr) {
    asm volatile("ldmatrix.sync.aligned.m8n8.x4.shared.b16 {%0,%1,%2,%3}, [%4];"
                 : "=r"(r0), "=r"(r1), "=r"(r2), "=r"(r3) : "r"(addr));
}
__device__ __forceinline__ void ldsm4_t(uint32_t& r0, uint32_t& r1, uint32_t& r2, uint32_t& r3,
                                        uint32_t addr) {
    asm volatile("ldmatrix.sync.aligned.m8n8.x4.trans.shared.b16 {%0,%1,%2,%3}, [%4];"
                 : "=r"(r0), "=r"(r1), "=r"(r2), "=r"(r3) : "r"(addr));
}

// 1-term chunk (A single, B single) — proj and fc.
template <int NF>
__device__ __forceinline__ void mma_chunk1(float (*acc)[4],
                                           uint32_t aH, uint32_t bH,
                                           int mw, int lane) {
    const int r  = lane & 7;
    const int q3 = (lane >> 3) & 1;
    const int q4 = (lane >> 4) & 1;
    const unsigned aoff = (unsigned)(((mw + q3 * 8 + r) * AST + q4 * 8) * 2);
    const unsigned boff = (unsigned)(((q4 * 8 + r) * AST + q3 * 8) * 2);
#pragma unroll
    for (int ks = 0; ks < 4; ks++) {
        uint32_t ah0, ah1, ah2, ah3;
        ldsm4(ah0, ah1, ah2, ah3, aH + aoff + ks * 32);
#pragma unroll
        for (int jp = 0; jp < NF / 2; jp++) {
            uint32_t bh0, bh1, bh2, bh3;
            unsigned bo = boff + (unsigned)(jp * 16 * AST * 2) + ks * 32;
            ldsm4(bh0, bh1, bh2, bh3, bH + bo);
            mma_bf16(acc[2 * jp],     ah0, ah1, ah2, ah3, bh0, bh1);
            mma_bf16(acc[2 * jp + 1], ah0, ah1, ah2, ah3, bh2, bh3);
        }
    }
}

__device__ __forceinline__ void cp_tile(char* dst, const char* src, int rows,
                                        int valid, int gstride, int tid, int nt) {
    for (int i = tid; i < rows * 8; i += nt) {
        int r = i >> 3, c = (i & 7) << 4;
        uint4 v = make_uint4(0u, 0u, 0u, 0u);
        if (r < valid) v = *(const uint4*)(src + (size_t)r * gstride + c);
        *(uint4*)(dst + r * (AST * 2) + c) = v;
    }
}

__device__ __forceinline__ void cpa16(uint32_t dst, const void* src) {
    asm volatile("cp.async.ca.shared.global [%0], [%1], 16;" :: "r"(dst), "l"(src));
}
#define CP_COMMIT() asm volatile("cp.async.commit_group;" ::: "memory")
#define CP_WAIT(n)  asm volatile("cp.async.wait_group %0;" :: "n"(n) : "memory")

__device__ __forceinline__ void cp_tile_async(uint32_t dst, const char* src,
                                              int rows8, int gstride, int tid, int nt) {
    for (int i = tid; i < rows8; i += nt) {
        int r = i >> 3, c = (i & 7) << 4;
        cpa16(dst + (unsigned)(r * (AST * 2) + c), src + (size_t)r * gstride + c);
    }
}

// ---------------------------------------------------------------------------
__global__ __launch_bounds__(256) void setup_w(const float* __restrict__ w_qs,
                                               const float* __restrict__ w_vs,
                                               const float* __restrict__ fcw,
                                               const float* __restrict__ w1,
                                               const float* __restrict__ w2,
                                               const float* __restrict__ b2) {
    int i0 = blockIdx.x * blockDim.x + threadIdx.x;
    int nt = gridDim.x * blockDim.x;
    for (int t = i0; t < FEAT * FEAT; t += nt) {
        int n = t >> 8, k = t & 255;
        g_wqsT[t] = __float2bfloat16(w_qs[k * FEAT + n]);
        g_wvsT[t] = __float2bfloat16(w_vs[k * FEAT + n]);
        g_fcwT[t] = __float2bfloat16(fcw [k * FEAT + n]);
    }
    for (int t = i0; t < DK * DK; t += nt) {
        int n = t >> 6, k = t & 63;
        split1(w1[k * DK + n], g_w1t_hi[t], g_w1t_lo[t]);
    }
    for (int t = i0; t < LPAD * DK; t += nt) {
        int n = t >> 6, k = t & 63;
        float f = (n < LSEQ) ? w2[k * LSEQ + n] : 0.f;
        g_w2t[t] = __float2bfloat16(f);
    }
    for (int t = i0; t < LPAD; t += nt)
        g_b2p[t] = (t < LSEQ) ? b2[t] : -1e30f;
}

// ---------------------------------------------------------------------------
// proj: merged heads, 1-term. CTA = 64 rows x 256 cols.
// grid (BATCH*8, 2), block 256, 3 CTAs/SM (45KB).
// ---------------------------------------------------------------------------
#define PR_A  0
#define PR_B  9216
#define PROJ_SMEM 46080

__global__ __launch_bounds__(256, 3) void proj_kernel(const float* __restrict__ q,
                                                      const float* __restrict__ v) {
    extern __shared__ char sm[];
    const uint32_t sb = smem_u32(sm);
    char* sA = sm + PR_A;

    const int tid = threadIdx.x;
    const int w = tid >> 5, lane = tid & 31, g = lane >> 2, tg = lane & 3;
    const int b = blockIdx.x >> 3, t = blockIdx.x & 7;
    const int which = blockIdx.y;
    const int l0 = t * 64;
    const int nrows = min(64, LSEQ - l0);
    const int m0 = b * LSEQ + l0;
    const int rg = w >> 1;
    const int nh = w & 1;
    const int mw = rg * 16;

    const float* X = which ? v : q;
    const __nv_bfloat16* W = which ? g_wvsT : g_wqsT;
    __nv_bfloat16* O = which ? g_vh : g_qh;

    float acc[16][4];
#pragma unroll
    for (int j = 0; j < 16; j++)
#pragma unroll
        for (int i = 0; i < 4; i++) acc[j][i] = 0.f;

    const uint32_t b_base = sb + PR_B + nh * 128 * (AST * 2);

    for (int kc = 0; kc < 4; kc++) {
        int k0 = kc * 64;
        __syncthreads();
        for (int i = tid; i < 64 * 16; i += 256) {
            int r = i >> 4, c4 = (i & 15) << 2;
            float4 a = make_float4(0.f, 0.f, 0.f, 0.f);
            if (r < nrows) a = *(const float4*)(X + (size_t)(m0 + r) * FEAT + k0 + c4);
            unsigned off = (unsigned)(r * (AST * 2) + c4 * 2);
            *(uint2*)(sA + off) = make_uint2(cvt2(a.x, a.y), cvt2(a.z, a.w));
        }
        cp_tile(sm + PR_B, (const char*)(W + k0), 256, 256, FEAT * 2, tid, 256);
        __syncthreads();
        mma_chunk1<16>(acc, sb + PR_A, b_base, mw, lane);
    }

#pragma unroll
    for (int rr = 0; rr < 2; rr++) {
        int ml = mw + g + rr * 8;
        if (ml >= nrows) continue;
        int l = l0 + ml;
#pragma unroll
        for (int j = 0; j < 16; j++) {
            int head = nh * 2 + (j >> 3);
            int d = (j & 7) * 8 + tg * 2;
            size_t base = ((size_t)(b * HEADS + head) * LSEQ + l) * DK + d;
            *(uint32_t*)(O + base) = cvt2(acc[j][rr * 2], acc[j][rr * 2 + 1]);
        }
    }
}

// ---------------------------------------------------------------------------
// synth: M-tile 64, 128 threads, 4 CTAs/SM (37.1KB). (unchanged from R15)
// ---------------------------------------------------------------------------
#define SY_SLOT 18432
#define SY_B1   (2*SY_SLOT)
#define SYN_SMEM (2*SY_SLOT + 256)

__global__ __launch_bounds__(128, 4) void synth_kernel(const float* __restrict__ b1) {
    extern __shared__ char sm[];
    const uint32_t sb = smem_u32(sm);
    float* b1s = (float*)(sm + SY_B1);

    const int tid = threadIdx.x;
    const int w = tid >> 5, lane = tid & 31, g = lane >> 2, tg = lane & 3;
    const int bh = blockIdx.y;
    const int r0 = blockIdx.x * 64;
    const int nrows = min(64, LSEQ - r0);
    const int mw = w * 16;

    const int r7 = lane & 7;
    const int q3 = (lane >> 3) & 1;
    const int q4 = (lane >> 4) & 1;
    const unsigned bo_n = (unsigned)(((q4 * 8 + r7) * AST + q3 * 8) * 2);
    const unsigned bo_t = (unsigned)(((q3 * 8 + r7) * AST + q4 * 8) * 2);

    const size_t vh_base = (size_t)bh * LSEQ * DK;
    const uint32_t w1b = sb + SY_SLOT;

    cp_tile_async(w1b,        (const char*)g_w1t_hi, 512, DK * 2, tid, 128);
    cp_tile_async(w1b + 9216, (const char*)g_w1t_lo, 512, DK * 2, tid, 128);
    CP_COMMIT();
    cp_tile_async(sb,        (const char*)g_w2t, 512, DK * 2, tid, 128);
    cp_tile_async(sb + 9216, (const char*)(g_vh + vh_base), 512, DK * 2, tid, 128);
    CP_COMMIT();
    if (tid < 64) b1s[tid] = b1[tid];

    uint32_t qf[4][4];
    {
        const size_t row0 = (size_t)bh * LSEQ + r0 + mw + g;
        const __nv_bfloat16* p0 = g_qh + row0 * DK;
        const __nv_bfloat16* p1 = p0 + 8 * DK;
#pragma unroll
        for (int ks = 0; ks < 4; ks++) {
            int col = ks * 16 + tg * 2;
            qf[ks][0] = *(const uint32_t*)(p0 + col);
            qf[ks][1] = *(const uint32_t*)(p1 + col);
            qf[ks][2] = *(const uint32_t*)(p0 + col + 8);
            qf[ks][3] = *(const uint32_t*)(p1 + col + 8);
        }
    }

    CP_WAIT(1);
    __syncthreads();

    uint32_t hf[4][4];
    {
        float accl[8][4];
#pragma unroll
        for (int j = 0; j < 8; j++)
#pragma unroll
            for (int i = 0; i < 4; i++) accl[j][i] = 0.f;
#pragma unroll
        for (int ks = 0; ks < 4; ks++) {
#pragma unroll
            for (int jp = 0; jp < 4; jp++) {
                uint32_t bh0, bh1, bh2, bh3, bl0, bl1, bl2, bl3;
                unsigned bo = bo_n + (unsigned)(jp * 16 * AST * 2) + ks * 32;
                ldsm4(bh0, bh1, bh2, bh3, w1b + bo);
                ldsm4(bl0, bl1, bl2, bl3, w1b + 9216 + bo);
                mma_bf16(accl[2 * jp],     qf[ks][0], qf[ks][1], qf[ks][2], qf[ks][3], bh0, bh1);
                mma_bf16(accl[2 * jp],     qf[ks][0], qf[ks][1], qf[ks][2], qf[ks][3], bl0, bl1);
                mma_bf16(accl[2 * jp + 1], qf[ks][0], qf[ks][1], qf[ks][2], qf[ks][3], bh2, bh3);
                mma_bf16(accl[2 * jp + 1], qf[ks][0], qf[ks][1], qf[ks][2], qf[ks][3], bl2, bl3);
            }
        }
#pragma unroll
        for (int s = 0; s < 4; s++) {
#pragma unroll
            for (int half = 0; half < 2; half++) {
                int j = 2 * s + half;
                float bb0 = b1s[j * 8 + tg * 2], bb1 = b1s[j * 8 + tg * 2 + 1];
                hf[s][half * 2]     = cvt2(fmaxf(accl[j][0] + bb0, 0.f),
                                           fmaxf(accl[j][1] + bb1, 0.f));
                hf[s][half * 2 + 1] = cvt2(fmaxf(accl[j][2] + bb0, 0.f),
                                           fmaxf(accl[j][3] + bb1, 0.f));
            }
        }
    }

    float acc_o[8][4];
#pragma unroll
    for (int j = 0; j < 8; j++)
#pragma unroll
        for (int i = 0; i < 4; i++) acc_o[j][i] = 0.f;
    float s0 = 0.f, s1 = 0.f;

    for (int c = 0; c < 8; c++) {
        CP_WAIT(0);
        __syncthreads();

        if (c + 1 < 8) {
            int cn = c + 1;
            uint32_t slot = sb + (cn & 1) * SY_SLOT;
            cp_tile_async(slot,        (const char*)(g_w2t + cn * 64 * DK), 512, DK * 2, tid, 128);
            cp_tile_async(slot + 9216, (const char*)(g_vh + vh_base + (size_t)cn * 64 * DK), 512, DK * 2, tid, 128);
        }
        CP_COMMIT();

        const uint32_t wb = sb + (c & 1) * SY_SLOT;
        const uint32_t vb = wb + 9216;

        float accl[8][4];
#pragma unroll
        for (int j = 0; j < 8; j++)
#pragma unroll
            for (int i = 0; i < 4; i++) accl[j][i] = 0.f;
#pragma unroll
        for (int ks = 0; ks < 4; ks++) {
#pragma unroll
            for (int jp = 0; jp < 4; jp++) {
                uint32_t bh0, bh1, bh2, bh3;
                unsigned bo = bo_n + (unsigned)(jp * 16 * AST * 2) + ks * 32;
                ldsm4(bh0, bh1, bh2, bh3, wb + bo);
                mma_bf16(accl[2 * jp],     hf[ks][0], hf[ks][1], hf[ks][2], hf[ks][3], bh0, bh1);
                mma_bf16(accl[2 * jp + 1], hf[ks][0], hf[ks][1], hf[ks][2], hf[ks][3], bh2, bh3);
            }
        }

        uint32_t pf[4][4];
        const int kc = c * 64;
#pragma unroll
        for (int s = 0; s < 4; s++) {
#pragma unroll
            for (int half = 0; half < 2; half++) {
                int j = 2 * s + half;
                int col = kc + j * 8 + tg * 2;
                float bb0 = __ldg(&g_b2p[col]), bb1 = __ldg(&g_b2p[col + 1]);
                float p0 = __expf(fminf(accl[j][0] + bb0, 80.f));
                float p1 = __expf(fminf(accl[j][1] + bb1, 80.f));
                float p2 = __expf(fminf(accl[j][2] + bb0, 80.f));
                float p3 = __expf(fminf(accl[j][3] + bb1, 80.f));
                s0 += p0 + p1;
                s1 += p2 + p3;
                pf[s][half * 2]     = cvt2(p0, p1);
                pf[s][half * 2 + 1] = cvt2(p2, p3);
            }
        }

#pragma unroll
        for (int ks = 0; ks < 4; ks++) {
#pragma unroll
            for (int jp = 0; jp < 4; jp++) {
                uint32_t bh0, bh1, bh2, bh3;
                unsigned bo = bo_t + (unsigned)(ks * 16 * AST * 2) + jp * 32;
                ldsm4_t(bh0, bh1, bh2, bh3, vb + bo);
                mma_bf16(acc_o[2 * jp],     pf[ks][0], pf[ks][1], pf[ks][2], pf[ks][3], bh0, bh1);
                mma_bf16(acc_o[2 * jp + 1], pf[ks][0], pf[ks][1], pf[ks][2], pf[ks][3], bh2, bh3);
            }
        }
    }

    s0 += __shfl_xor_sync(0xffffffffu, s0, 1);
    s0 += __shfl_xor_sync(0xffffffffu, s0, 2);
    s1 += __shfl_xor_sync(0xffffffffu, s1, 1);
    s1 += __shfl_xor_sync(0xffffffffu, s1, 2);
    const float inv0 = 1.f / s0, inv1 = 1.f / s1;
    const int b = bh >> 2, hh = bh & 3;
#pragma unroll
    for (int rr = 0; rr < 2; rr++) {
        int ml = mw + g + rr * 8;
        if (ml >= nrows) continue;
        float invv = rr ? inv1 : inv0;
        size_t base = ((size_t)(b * LSEQ + r0 + ml)) * FEAT + hh * 64;
#pragma unroll
        for (int j = 0; j < 8; j++) {
            *(uint32_t*)(g_pre + base + j * 8 + tg * 2) =
                cvt2(acc_o[j][rr * 2] * invv, acc_o[j][rr * 2 + 1] * invv);
        }
    }
}

// ---------------------------------------------------------------------------
// fc + residual + LayerNorm. 1-term mma (A single, fcw single).
// grid 500, block 256, 64 rows/CTA, 3 CTAs/SM (45KB).
// ---------------------------------------------------------------------------
#define FC_A  0
#define FC_B  9216
#define FC_SMEM 46080

__global__ __launch_bounds__(256, 3) void fc_ln_kernel(const float* __restrict__ q,
                                                       const float* __restrict__ lng,
                                                       const float* __restrict__ lnb,
                                                       float* __restrict__ out) {
    extern __shared__ char sm[];
    const uint32_t sb = smem_u32(sm);
    float* partial = (float*)sm;

    const int tid = threadIdx.x;
    const int w = tid >> 5, lane = tid & 31, g = lane >> 2, tg = lane & 3;
    const int m0 = blockIdx.x * 64;
    const int rg = w >> 1;
    const int nh = w & 1;
    const int mw = rg * 16;

    float acc[16][4];
#pragma unroll
    for (int j = 0; j < 16; j++)
#pragma unroll
        for (int i = 0; i < 4; i++) acc[j][i] = 0.f;

    const uint32_t b_base = sb + FC_B + nh * 128 * (AST * 2);

    for (int kc = 0; kc < 4; kc++) {
        int k0 = kc * 64;
        __syncthreads();
        cp_tile(sm + FC_A, (const char*)(g_pre + (size_t)m0 * FEAT + k0), 64, 64, FEAT * 2, tid, 256);
        cp_tile(sm + FC_B, (const char*)(g_fcwT + k0), 256, 256, FEAT * 2, tid, 256);
        __syncthreads();
        mma_chunk1<16>(acc, sb + FC_A, b_base, mw, lane);
    }
    __syncthreads();

    float sums[2][2];
#pragma unroll
    for (int rr = 0; rr < 2; rr++) {
        int r = mw + g + rr * 8;
        const float* qrow = q + (size_t)(m0 + r) * FEAT + nh * 128;
        float s = 0.f, s2 = 0.f;
#pragma unroll
        for (int j = 0; j < 16; j++) {
            float2 qq = *(const float2*)(qrow + j * 8 + tg * 2);
            float x0 = acc[j][rr * 2]     + qq.x;
            float x1 = acc[j][rr * 2 + 1] + qq.y;
            acc[j][rr * 2] = x0;
            acc[j][rr * 2 + 1] = x1;
            s += x0 + x1;
            s2 += x0 * x0 + x1 * x1;
        }
        s  += __shfl_xor_sync(0xffffffffu, s, 1);
        s  += __shfl_xor_sync(0xffffffffu, s, 2);
        s2 += __shfl_xor_sync(0xffffffffu, s2, 1);
        s2 += __shfl_xor_sync(0xffffffffu, s2, 2);
        sums[rr][0] = s;
        sums[rr][1] = s2;
        if (tg == 0) {
            partial[(r * 2 + nh) * 2 + 0] = s;
            partial[(r * 2 + nh) * 2 + 1] = s2;
        }
    }
    __syncthreads();

#pragma unroll
    for (int rr = 0; rr < 2; rr++) {
        int r = mw + g + rr * 8;
        float s  = sums[rr][0] + partial[(r * 2 + (nh ^ 1)) * 2 + 0];
        float s2 = sums[rr][1] + partial[(r * 2 + (nh ^ 1)) * 2 + 1];
        float mu = s * (1.f / FEAT);
        float rstd = rsqrtf(s2 * (1.f / FEAT) - mu * mu + 1e-6f);
        float* orow = out + (size_t)(m0 + r) * FEAT + nh * 128;
#pragma unroll
        for (int j = 0; j < 16; j++) {
            int col = nh * 128 + j * 8 + tg * 2;
            float g0 = __ldg(&lng[col]), g1 = __ldg(&lng[col + 1]);
            float bb0 = __ldg(&lnb[col]), bb1 = __ldg(&lnb[col + 1]);
            float2 o;
            o.x = (acc[j][rr * 2]     - mu) * rstd * g0 + bb0;
            o.y = (acc[j][rr * 2 + 1] - mu) * rstd * g1 + bb1;
            *(float2*)(orow + col - nh * 128) = o;
        }
    }
}

// ---------------------------------------------------------------------------
extern "C" void kernel_launch(void* const* d_in, const int* in_sizes, int n_in,
                              void* d_out, int out_size)
{
    (void)in_sizes; (void)n_in; (void)out_size;
    const float* q    = (const float*)d_in[0];
    const float* v    = (const float*)d_in[2];
    const float* w_qs = (const float*)d_in[3];
    const float* w_vs = (const float*)d_in[4];
    const float* w1   = (const float*)d_in[5];
    const float* b1   = (const float*)d_in[6];
    const float* w2   = (const float*)d_in[7];
    const float* b2   = (const float*)d_in[8];
    const float* fcw  = (const float*)d_in[9];
    const float* lng  = (const float*)d_in[10];
    const float* lnb  = (const float*)d_in[11];
    float* out = (float*)d_out;

    cudaFuncSetAttribute(proj_kernel,  cudaFuncAttributeMaxDynamicSharedMemorySize, PROJ_SMEM);
    cudaFuncSetAttribute(synth_kernel, cudaFuncAttributeMaxDynamicSharedMemorySize, SYN_SMEM);
    cudaFuncSetAttribute(fc_ln_kernel, cudaFuncAttributeMaxDynamicSharedMemorySize, FC_SMEM);

    setup_w<<<128, 256>>>(w_qs, w_vs, fcw, w1, w2, b2);
    proj_kernel<<<dim3(BATCH * 8, 2), 256, PROJ_SMEM>>>(q, v);
    synth_kernel<<<dim3(8, BH), 128, SYN_SMEM>>>(b1);
    fc_ln_kernel<<<500, 256, FC_SMEM>>>(q, lng, lnb, out);
}